// round 1
// baseline (speedup 1.0000x reference)
#include <cuda_runtime.h>
#include <cuda_fp16.h>
#include <mma.h>

using namespace nvcuda;

// Problem dims
#define DD    1024
#define NB    8
#define NS    2048
#define MTOT  (NB * NS)        // 16384
#define NQKV  (3 * DD)         // 3072
#define KPQ   2048             // packed K for QKV gemm (512 hi.hi low-bands + 3*512 middle)

// GEMM tiling
#define BM 128
#define BN 128
#define BK 32
#define LDA_S 40               // BK + 8 pad (halves)
#define LDB_NN 136             // BN + 8 pad (halves)

// ---------------- scratch (device globals; no runtime allocation) ----------------
__device__ __align__(16) half  g_Ap  [(size_t)MTOT * KPQ];     // packed x operand  (67 MB)
__device__ __align__(16) half  g_Bp  [(size_t)NQKV * KPQ];     // packed w operand  (12.6 MB)
__device__ __align__(16) half  g_qkvh[(size_t)MTOT * NQKV];    // hi(qkv), q pre-scaled (100 MB)
__device__ __align__(16) half  g_qkvl[(size_t)MTOT * NQKV];    // lo(qkv)           (100 MB)
__device__ __align__(16) float g_logits[(size_t)NB * NS * NS]; // attention logits  (134 MB)
__device__ __align__(16) half  g_sh [(size_t)NB * NS * NS];    // hi(softmax)       (67 MB)
__device__ __align__(16) half  g_sl [(size_t)NB * NS * NS];    // lo(softmax)       (67 MB)
__device__ __align__(16) half  g_yh [(size_t)MTOT * DD];       // hi(y)             (33.5 MB)
__device__ __align__(16) half  g_yl [(size_t)MTOT * DD];       // lo(y)             (33.5 MB)
__device__ __align__(16) half  g_owh[(size_t)DD * DD];         // hi(out_w)
__device__ __align__(16) half  g_owl[(size_t)DD * DD];         // lo(out_w)

enum { SEG_AP = 0, SEG_BP, SEG_QKVH, SEG_QKVL, SEG_SH, SEG_SL, SEG_YH, SEG_YL, SEG_OWH, SEG_OWL };

__device__ __forceinline__ const half* seg_ptr(int id) {
    switch (id) {
        case SEG_AP:   return g_Ap;
        case SEG_BP:   return g_Bp;
        case SEG_QKVH: return g_qkvh;
        case SEG_QKVL: return g_qkvl;
        case SEG_SH:   return g_sh;
        case SEG_SL:   return g_sl;
        case SEG_YH:   return g_yh;
        case SEG_YL:   return g_yl;
        case SEG_OWH:  return g_owh;
        case SEG_OWL:  return g_owl;
    }
    return nullptr;
}

// ---------------- hi/lo split helpers ----------------
__device__ __forceinline__ half f_hi(float v) { return __float2half_rn(v); }
__device__ __forceinline__ half f_lo(float v) {
    half h = __float2half_rn(v);
    return __float2half_rn(v - __half2float(h));
}

// K'-mapping for the packed QKV GEMM.
// Reference splits contraction dim 1024 into [0,256) fp16 | [256,768) fp32 | [768,1024) fp16.
// k' in [0,256)    : low band 1, hi.hi
// k' in [256,512)  : low band 2, hi.hi
// k' in [512,1024) : middle, hi.hi
// k' in [1024,1536): middle, hi(A).lo(B)
// k' in [1536,2048): middle, lo(A).hi(B)
__device__ __forceinline__ void map_k(int kp, int& src, bool& alo, bool& blo) {
    alo = false; blo = false;
    if (kp < 256)        { src = kp; }
    else if (kp < 512)   { src = 768 + (kp - 256); }
    else if (kp < 1024)  { src = 256 + (kp - 512); }
    else if (kp < 1536)  { src = 256 + (kp - 1024); blo = true; }
    else                 { src = 256 + (kp - 1536); alo = true; }
}

// ---------------- prep kernels ----------------
__global__ void prep_A(const float* __restrict__ x) {
    long long idx = (long long)blockIdx.x * blockDim.x + threadIdx.x;
    if (idx >= (long long)MTOT * KPQ) return;
    int kp = (int)(idx & (KPQ - 1));
    long long m = idx >> 11;
    int src; bool alo, blo;
    map_k(kp, src, alo, blo);
    float v = x[m * DD + src];
    g_Ap[idx] = alo ? f_lo(v) : f_hi(v);
}

__global__ void prep_B(const float* __restrict__ w) {
    long long idx = (long long)blockIdx.x * blockDim.x + threadIdx.x;
    if (idx >= (long long)NQKV * KPQ) return;
    int kp = (int)(idx & (KPQ - 1));
    int n  = (int)(idx >> 11);
    int src; bool alo, blo;
    map_k(kp, src, alo, blo);
    float v = w[(long long)src * NQKV + n];
    g_Bp[idx] = blo ? f_lo(v) : f_hi(v);
}

__global__ void prep_OW(const float* __restrict__ ow) {
    int idx = blockIdx.x * blockDim.x + threadIdx.x;
    if (idx >= DD * DD) return;
    float v = ow[idx];
    g_owh[idx] = f_hi(v);
    g_owl[idx] = f_lo(v);
}

// ---------------- GEMM ----------------
struct GemmArgs {
    long long aoff[3];
    long long boff[3];
    long long az, bz;      // per-batch element strides
    int aid[3];
    int bid[3];
    int lda, ldb;
    int K, nseg;
};

enum { EPI_QKV = 0, EPI_LOGITS = 1, EPI_SPLIT_Y = 2, EPI_OUT = 3 };

template <int EPI, bool BNT>
__global__ __launch_bounds__(256) void gemm_kernel(GemmArgs ga, float* __restrict__ outp,
                                                   const float* __restrict__ bias) {
    __shared__ __align__(16) half  As[BM * LDA_S];           // 10240 B
    __shared__ __align__(16) half  Bs[BM * LDA_S];           // 10240 B (NN uses 32*136 < this)
    __shared__ __align__(16) float Cs[8 * 16 * 20];          // 10240 B

    const int tid  = threadIdx.x;
    const int warp = tid >> 5;
    const int lane = tid & 31;
    const int wm = warp >> 1;      // 0..3
    const int wn = warp & 1;       // 0..1
    const int m0 = blockIdx.y * BM;
    const int n0 = blockIdx.x * BN;
    const int z  = blockIdx.z;

    wmma::fragment<wmma::accumulator, 16, 16, 16, float> acc[2][4];
#pragma unroll
    for (int i = 0; i < 2; i++)
#pragma unroll
        for (int j = 0; j < 4; j++) wmma::fill_fragment(acc[i][j], 0.0f);

    for (int s = 0; s < ga.nseg; s++) {
        const half* A = seg_ptr(ga.aid[s]) + (long long)z * ga.az + ga.aoff[s];
        const half* B = seg_ptr(ga.bid[s]) + (long long)z * ga.bz + ga.boff[s];

        for (int k0 = 0; k0 < ga.K; k0 += BK) {
            // A tile: [BM rows][BK cols], row-major
#pragma unroll
            for (int i = 0; i < 2; i++) {
                int slot = tid + i * 256;
                int r = slot >> 2;
                int c = (slot & 3) * 8;
                *(uint4*)&As[r * LDA_S + c] =
                    *(const uint4*)&A[(long long)(m0 + r) * ga.lda + k0 + c];
            }
            if (BNT) {
                // B[n][k] row-major -> smem [n][k] (wmma col_major view of [k][n])
#pragma unroll
                for (int i = 0; i < 2; i++) {
                    int slot = tid + i * 256;
                    int r = slot >> 2;
                    int c = (slot & 3) * 8;
                    *(uint4*)&Bs[r * LDA_S + c] =
                        *(const uint4*)&B[(long long)(n0 + r) * ga.ldb + k0 + c];
                }
            } else {
                // B[k][n] row-major -> smem [k][n] (wmma row_major matrix_b)
#pragma unroll
                for (int i = 0; i < 2; i++) {
                    int slot = tid + i * 256;
                    int r = slot >> 4;
                    int c = (slot & 15) * 8;
                    *(uint4*)&Bs[r * LDB_NN + c] =
                        *(const uint4*)&B[(long long)(k0 + r) * ga.ldb + n0 + c];
                }
            }
            __syncthreads();

#pragma unroll
            for (int kk = 0; kk < BK; kk += 16) {
                wmma::fragment<wmma::matrix_a, 16, 16, 16, half, wmma::row_major> af[2];
#pragma unroll
                for (int i = 0; i < 2; i++)
                    wmma::load_matrix_sync(af[i], &As[(wm * 32 + i * 16) * LDA_S + kk], LDA_S);
#pragma unroll
                for (int j = 0; j < 4; j++) {
                    if constexpr (BNT) {
                        wmma::fragment<wmma::matrix_b, 16, 16, 16, half, wmma::col_major> bf;
                        wmma::load_matrix_sync(bf, &Bs[(wn * 64 + j * 16) * LDA_S + kk], LDA_S);
#pragma unroll
                        for (int i = 0; i < 2; i++) wmma::mma_sync(acc[i][j], af[i], bf, acc[i][j]);
                    } else {
                        wmma::fragment<wmma::matrix_b, 16, 16, 16, half, wmma::row_major> bf;
                        wmma::load_matrix_sync(bf, &Bs[kk * LDB_NN + wn * 64 + j * 16], LDB_NN);
#pragma unroll
                        for (int i = 0; i < 2; i++) wmma::mma_sync(acc[i][j], af[i], bf, acc[i][j]);
                    }
                }
            }
            __syncthreads();
        }
    }

    // ---------------- epilogue ----------------
    if (EPI == EPI_LOGITS) {
#pragma unroll
        for (int i = 0; i < 2; i++)
#pragma unroll
            for (int j = 0; j < 4; j++) {
                long long row = (long long)z * NS + m0 + wm * 32 + i * 16;
                float* dst = g_logits + row * NS + n0 + wn * 64 + j * 16;
                wmma::store_matrix_sync(dst, acc[i][j], NS, wmma::mem_row_major);
            }
        return;
    }

    float* cw = &Cs[warp * 16 * 20];
#pragma unroll
    for (int i = 0; i < 2; i++) {
#pragma unroll
        for (int j = 0; j < 4; j++) {
            wmma::store_matrix_sync(cw, acc[i][j], 20, wmma::mem_row_major);
            __syncwarp();
#pragma unroll
            for (int e = 0; e < 8; e++) {
                int el = lane * 8 + e;
                int r = el >> 4;
                int c = el & 15;
                float v = cw[r * 20 + c];
                long long m = m0 + wm * 32 + i * 16 + r;
                long long n = n0 + wn * 64 + j * 16 + c;
                if (EPI == EPI_QKV) {
                    // fold the q/sqrt(d) scaling in before the hi/lo re-split
                    float v2 = v * ((n < DD) ? 0.03125f : 1.0f);
                    half h = __float2half_rn(v2);
                    long long o = m * NQKV + n;
                    g_qkvh[o] = h;
                    g_qkvl[o] = __float2half_rn(v2 - __half2float(h));
                } else if (EPI == EPI_SPLIT_Y) {
                    long long row = (long long)z * NS + m;
                    half h = __float2half_rn(v);
                    long long o = row * DD + n;
                    g_yh[o] = h;
                    g_yl[o] = __float2half_rn(v - __half2float(h));
                } else { // EPI_OUT
                    outp[m * DD + n] = v + bias[n];
                }
            }
            __syncwarp();
        }
    }
}

// ---------------- softmax (per row of logits), writes hi/lo fp16 probs ----------------
__global__ __launch_bounds__(256) void softmax_kernel() {
    const long long row = blockIdx.x;
    const float* __restrict__ L = g_logits + row * (long long)NS;
    const int tid = threadIdx.x;

    float lv[8];
    float mx = -3.4e38f;
#pragma unroll
    for (int i = 0; i < 8; i++) {
        lv[i] = L[tid + i * 256];
        mx = fmaxf(mx, lv[i]);
    }
#pragma unroll
    for (int o = 16; o; o >>= 1) mx = fmaxf(mx, __shfl_xor_sync(0xffffffffu, mx, o));
    __shared__ float smax[8];
    __shared__ float ssum[8];
    if ((tid & 31) == 0) smax[tid >> 5] = mx;
    __syncthreads();
    float bmax = smax[0];
#pragma unroll
    for (int i = 1; i < 8; i++) bmax = fmaxf(bmax, smax[i]);

    float s = 0.0f;
#pragma unroll
    for (int i = 0; i < 8; i++) {
        lv[i] = __expf(lv[i] - bmax);
        s += lv[i];
    }
#pragma unroll
    for (int o = 16; o; o >>= 1) s += __shfl_xor_sync(0xffffffffu, s, o);
    if ((tid & 31) == 0) ssum[tid >> 5] = s;
    __syncthreads();
    float tot = 0.0f;
#pragma unroll
    for (int i = 0; i < 8; i++) tot += ssum[i];
    float inv = 1.0f / tot;

#pragma unroll
    for (int i = 0; i < 8; i++) {
        float p = lv[i] * inv;
        half h = __float2half_rn(p);
        long long o = row * NS + tid + i * 256;
        g_sh[o] = h;
        g_sl[o] = __float2half_rn(p - __half2float(h));
    }
}

// ---------------- launch ----------------
extern "C" void kernel_launch(void* const* d_in, const int* in_sizes, int n_in,
                              void* d_out, int out_size) {
    const float *x = nullptr, *wq = nullptr, *ow = nullptr, *ob = nullptr;
    for (int i = 0; i < n_in; i++) {
        long long sz = in_sizes[i];
        if (sz == (long long)MTOT * DD)      x  = (const float*)d_in[i];
        else if (sz == (long long)DD * NQKV) wq = (const float*)d_in[i];
        else if (sz == (long long)DD * DD)   ow = (const float*)d_in[i];
        else if (sz == DD)                   ob = (const float*)d_in[i];
    }
    if (!x)  x  = (const float*)d_in[0];
    if (!wq) wq = (const float*)d_in[1];
    if (!ow) ow = (const float*)d_in[2];
    if (!ob) ob = (const float*)d_in[3];
    float* out = (float*)d_out;

    prep_A<<<(int)(((long long)MTOT * KPQ) / 256), 256>>>(x);
    prep_B<<<(int)(((long long)NQKV * KPQ) / 256), 256>>>(wq);
    prep_OW<<<(DD * DD) / 256, 256>>>(ow);

    // 1) QKV: [16384 x 2048] * [3072 x 2048]^T  -> hi/lo qkv (q pre-scaled)
    {
        GemmArgs ga{};
        ga.nseg = 1; ga.K = KPQ;
        ga.aid[0] = SEG_AP; ga.aoff[0] = 0; ga.az = 0; ga.lda = KPQ;
        ga.bid[0] = SEG_BP; ga.boff[0] = 0; ga.bz = 0; ga.ldb = KPQ;
        gemm_kernel<EPI_QKV, true><<<dim3(NQKV / BN, MTOT / BM, 1), 256>>>(ga, nullptr, nullptr);
    }
    // 2) QK^T per batch: 3 hi/lo segments -> fp32 logits
    {
        GemmArgs ga{};
        ga.nseg = 3; ga.K = DD; ga.lda = NQKV; ga.ldb = NQKV;
        ga.az = (long long)NS * NQKV; ga.bz = (long long)NS * NQKV;
        ga.aid[0] = SEG_QKVH; ga.aoff[0] = 0; ga.bid[0] = SEG_QKVH; ga.boff[0] = DD;
        ga.aid[1] = SEG_QKVH; ga.aoff[1] = 0; ga.bid[1] = SEG_QKVL; ga.boff[1] = DD;
        ga.aid[2] = SEG_QKVL; ga.aoff[2] = 0; ga.bid[2] = SEG_QKVH; ga.boff[2] = DD;
        gemm_kernel<EPI_LOGITS, true><<<dim3(NS / BN, NS / BM, NB), 256>>>(ga, nullptr, nullptr);
    }
    // 3) softmax rows -> hi/lo probs
    softmax_kernel<<<MTOT, 256>>>();
    // 4) S*V per batch (NN): 3 segments -> hi/lo y
    {
        GemmArgs ga{};
        ga.nseg = 3; ga.K = NS; ga.lda = NS; ga.ldb = NQKV;
        ga.az = (long long)NS * NS; ga.bz = (long long)NS * NQKV;
        ga.aid[0] = SEG_SH; ga.aoff[0] = 0; ga.bid[0] = SEG_QKVH; ga.boff[0] = 2 * DD;
        ga.aid[1] = SEG_SH; ga.aoff[1] = 0; ga.bid[1] = SEG_QKVL; ga.boff[1] = 2 * DD;
        ga.aid[2] = SEG_SL; ga.aoff[2] = 0; ga.bid[2] = SEG_QKVH; ga.boff[2] = 2 * DD;
        gemm_kernel<EPI_SPLIT_Y, false><<<dim3(DD / BN, NS / BM, NB), 256>>>(ga, nullptr, nullptr);
    }
    // 5) out = y @ out_w^T + b  (NT): 3 segments -> fp32 output
    {
        GemmArgs ga{};
        ga.nseg = 3; ga.K = DD; ga.lda = DD; ga.ldb = DD; ga.az = 0; ga.bz = 0;
        ga.aid[0] = SEG_YH; ga.aoff[0] = 0; ga.bid[0] = SEG_OWH; ga.boff[0] = 0;
        ga.aid[1] = SEG_YH; ga.aoff[1] = 0; ga.bid[1] = SEG_OWL; ga.boff[1] = 0;
        ga.aid[2] = SEG_YL; ga.aoff[2] = 0; ga.bid[2] = SEG_OWH; ga.boff[2] = 0;
        gemm_kernel<EPI_OUT, true><<<dim3(DD / BN, MTOT / BM, 1), 256>>>(ga, out, ob);
    }
}

// round 3
// speedup vs baseline: 1.0586x; 1.0586x over previous
#include <cuda_runtime.h>
#include <cuda_fp16.h>
#include <cstdint>

// Problem dims
#define DD    1024
#define NB    8
#define NS    2048
#define MTOT  (NB * NS)        // 16384
#define NQKV  (3 * DD)         // 3072
#define KPQ   2048             // packed K for QKV gemm

// GEMM tiling: block 256x128, 512 threads (16 warps, 4M x 4N), warp 64x32
#define BM 256
#define BN 128
#define BKH 32                 // K halves per stage
#define LDS_ 40                // padded smem stride (halves); rows 80B, 16B-aligned chunks
#define STG 4
#define A_ST (BM * LDS_)       // 10240 halves per A stage
#define B_ST (BN * LDS_)       // 5120 halves per B stage
#define SMEM_BYTES (STG * (A_ST + B_ST) * 2)   // 122880

// ---------------- scratch (device globals; no runtime allocation) ----------------
__device__ __align__(16) half  g_Ap  [(size_t)MTOT * KPQ];     // packed x operand
__device__ __align__(16) half  g_Bp  [(size_t)NQKV * KPQ];     // packed w operand
__device__ __align__(16) half  g_qkvh[(size_t)MTOT * NQKV];    // hi(qkv), q pre-scaled
__device__ __align__(16) half  g_qkvl[(size_t)MTOT * NQKV];    // lo(qkv)
__device__ __align__(16) float g_logits[(size_t)NB * NS * NS]; // attention logits
__device__ __align__(16) half  g_sh [(size_t)NB * NS * NS];    // hi(softmax)
__device__ __align__(16) half  g_sl [(size_t)NB * NS * NS];    // lo(softmax)
__device__ __align__(16) half  g_yh [(size_t)MTOT * DD];       // hi(y)
__device__ __align__(16) half  g_yl [(size_t)MTOT * DD];       // lo(y)
__device__ __align__(16) half  g_owh[(size_t)DD * DD];         // hi(out_w)
__device__ __align__(16) half  g_owl[(size_t)DD * DD];         // lo(out_w)
__device__ __align__(16) half  g_vth[(size_t)NB * DD * NS];    // hi(V^T)  [z][n][k]
__device__ __align__(16) half  g_vtl[(size_t)NB * DD * NS];    // lo(V^T)

enum { SEG_AP = 0, SEG_BP, SEG_QKVH, SEG_QKVL, SEG_SH, SEG_SL, SEG_YH, SEG_YL,
       SEG_OWH, SEG_OWL, SEG_VTH, SEG_VTL };

__device__ __forceinline__ const half* seg_ptr(int id) {
    switch (id) {
        case SEG_AP:   return g_Ap;
        case SEG_BP:   return g_Bp;
        case SEG_QKVH: return g_qkvh;
        case SEG_QKVL: return g_qkvl;
        case SEG_SH:   return g_sh;
        case SEG_SL:   return g_sl;
        case SEG_YH:   return g_yh;
        case SEG_YL:   return g_yl;
        case SEG_OWH:  return g_owh;
        case SEG_OWL:  return g_owl;
        case SEG_VTH:  return g_vth;
        case SEG_VTL:  return g_vtl;
    }
    return nullptr;
}

// ---------------- PTX helpers ----------------
__device__ __forceinline__ uint32_t smem_u32(const void* p) {
    uint32_t a;
    asm("{ .reg .u64 t; cvta.to.shared.u64 t, %1; cvt.u32.u64 %0, t; }" : "=r"(a) : "l"(p));
    return a;
}

#define CP_ASYNC16(dst, src) \
    asm volatile("cp.async.cg.shared.global [%0], [%1], 16;\n" :: "r"(dst), "l"(src))
#define CP_COMMIT() asm volatile("cp.async.commit_group;\n" ::: "memory")
#define CP_WAIT2()  asm volatile("cp.async.wait_group 2;\n" ::: "memory")
#define CP_WAIT0()  asm volatile("cp.async.wait_group 0;\n" ::: "memory")

__device__ __forceinline__ void ldsm_x4(uint32_t& r0, uint32_t& r1, uint32_t& r2,
                                        uint32_t& r3, uint32_t addr) {
    asm volatile("ldmatrix.sync.aligned.m8n8.x4.shared.b16 {%0,%1,%2,%3}, [%4];"
                 : "=r"(r0), "=r"(r1), "=r"(r2), "=r"(r3) : "r"(addr));
}

__device__ __forceinline__ void mma16816(float* d, const uint32_t* a, const uint32_t* b) {
    asm volatile("mma.sync.aligned.m16n8k16.row.col.f32.f16.f16.f32 "
                 "{%0,%1,%2,%3}, {%4,%5,%6,%7}, {%8,%9}, {%0,%1,%2,%3};"
                 : "+f"(d[0]), "+f"(d[1]), "+f"(d[2]), "+f"(d[3])
                 : "r"(a[0]), "r"(a[1]), "r"(a[2]), "r"(a[3]), "r"(b[0]), "r"(b[1]));
}

// ---------------- hi/lo split helpers ----------------
__device__ __forceinline__ half f_hi(float v) { return __float2half_rn(v); }
__device__ __forceinline__ half f_lo(float v) {
    half h = __float2half_rn(v);
    return __float2half_rn(v - __half2float(h));
}

// K'-mapping for the packed QKV GEMM.
// Reference splits contraction dim 1024 into [0,256) fp16 | [256,768) fp32 | [768,1024) fp16.
__device__ __forceinline__ void map_k(int kp, int& src, bool& alo, bool& blo) {
    alo = false; blo = false;
    if (kp < 256)        { src = kp; }
    else if (kp < 512)   { src = 768 + (kp - 256); }
    else if (kp < 1024)  { src = 256 + (kp - 512); }
    else if (kp < 1536)  { src = 256 + (kp - 1024); blo = true; }
    else                 { src = 256 + (kp - 1536); alo = true; }
}

// ---------------- prep kernels ----------------
__global__ void prep_A(const float* __restrict__ x) {
    long long idx = (long long)blockIdx.x * blockDim.x + threadIdx.x;
    if (idx >= (long long)MTOT * KPQ) return;
    int kp = (int)(idx & (KPQ - 1));
    long long m = idx >> 11;
    int src; bool alo, blo;
    map_k(kp, src, alo, blo);
    float v = x[m * DD + src];
    g_Ap[idx] = alo ? f_lo(v) : f_hi(v);
}

__global__ void prep_B(const float* __restrict__ w) {
    long long idx = (long long)blockIdx.x * blockDim.x + threadIdx.x;
    if (idx >= (long long)NQKV * KPQ) return;
    int kp = (int)(idx & (KPQ - 1));
    int n  = (int)(idx >> 11);
    int src; bool alo, blo;
    map_k(kp, src, alo, blo);
    float v = w[(long long)src * NQKV + n];
    g_Bp[idx] = blo ? f_lo(v) : f_hi(v);
}

__global__ void prep_OW(const float* __restrict__ ow) {
    int idx = blockIdx.x * blockDim.x + threadIdx.x;
    if (idx >= DD * DD) return;
    float v = ow[idx];
    g_owh[idx] = f_hi(v);
    g_owl[idx] = f_lo(v);
}

// V transpose: g_qkv{h,l}[z][k][2*DD + n] -> g_vt{h,l}[z][n][k]
__global__ void transpose_v() {
    __shared__ half th[32][33];
    __shared__ half tl[32][33];
    const int z  = blockIdx.z;
    const int k0 = blockIdx.x * 32;
    const int n0 = blockIdx.y * 32;
    const int tx = threadIdx.x;
    const int ty = threadIdx.y;
#pragma unroll
    for (int i = 0; i < 32; i += 8) {
        long long src = ((long long)(z * NS + k0 + ty + i)) * NQKV + 2 * DD + n0 + tx;
        th[ty + i][tx] = g_qkvh[src];
        tl[ty + i][tx] = g_qkvl[src];
    }
    __syncthreads();
#pragma unroll
    for (int i = 0; i < 32; i += 8) {
        long long dst = ((long long)(z * DD + n0 + ty + i)) * NS + k0 + tx;
        g_vth[dst] = th[tx][ty + i];
        g_vtl[dst] = tl[tx][ty + i];
    }
}

// ---------------- GEMM ----------------
struct GemmArgs {
    long long aoff[3];
    long long boff[3];
    long long az, bz;      // per-batch element strides
    int aid[3];
    int bid[3];
    int lda, ldb;          // row strides (halves); K contiguous (all gemms NT)
    int K, nseg;
};

enum { EPI_QKV = 0, EPI_LOGITS = 1, EPI_SPLIT_Y = 2, EPI_OUT = 3 };

__device__ __forceinline__ void stage_load(const GemmArgs& ga, int s, int spseg,
                                           int m0, int n0, int z,
                                           half* sA, half* sB, int tid) {
    const int seg = s / spseg;
    const int k0  = (s - seg * spseg) * BKH;
    const half* A = seg_ptr(ga.aid[seg]) + (long long)z * ga.az + ga.aoff[seg];
    const half* B = seg_ptr(ga.bid[seg]) + (long long)z * ga.bz + ga.boff[seg];
    const int buf = s & (STG - 1);
    const uint32_t sa = smem_u32(sA + buf * A_ST);
    const uint32_t sb = smem_u32(sB + buf * B_ST);

    // A: BM(256) rows x 64B -> 1024 16B-chunks, 2 per thread
#pragma unroll
    for (int i = 0; i < 2; i++) {
        int c = tid + i * 512;
        int r = c >> 2;
        int kc = (c & 3) * 8;      // halves
        CP_ASYNC16(sa + (uint32_t)(r * LDS_ + kc) * 2,
                   A + (long long)(m0 + r) * ga.lda + k0 + kc);
    }
    // B: BN(128) rows x 64B -> 512 16B-chunks, 1 per thread
    {
        int r = tid >> 2;
        int kc = (tid & 3) * 8;
        CP_ASYNC16(sb + (uint32_t)(r * LDS_ + kc) * 2,
                   B + (long long)(n0 + r) * ga.ldb + k0 + kc);
    }
}

template <int EPI>
__global__ __launch_bounds__(512, 1) void mg_gemm(GemmArgs ga, float* __restrict__ outp,
                                                  const float* __restrict__ bias) {
    extern __shared__ half sm[];
    half* sA = sm;                 // [STG][A_ST]
    half* sB = sm + STG * A_ST;    // [STG][B_ST]

    const int tid  = threadIdx.x;
    const int warp = tid >> 5;
    const int lane = tid & 31;
    const int wm = warp >> 2;      // 0..3  (M)
    const int wn = warp & 3;       // 0..3  (N)
    const int m0 = blockIdx.y * BM;
    const int n0 = blockIdx.x * BN;
    const int z  = blockIdx.z;

    float acc[4][4][4];
#pragma unroll
    for (int i = 0; i < 4; i++)
#pragma unroll
        for (int j = 0; j < 4; j++)
#pragma unroll
            for (int e = 0; e < 4; e++) acc[i][j][e] = 0.0f;

    const int spseg = ga.K / BKH;
    const int S = ga.nseg * spseg;

    // prologue: fill STG-1 stages
#pragma unroll
    for (int p = 0; p < STG - 1; p++) {
        stage_load(ga, p, spseg, m0, n0, z, sA, sB, tid);
        CP_COMMIT();
    }

    for (int s = 0; s < S; s++) {
        CP_WAIT2();                // stage s data resident
        __syncthreads();           // everyone done reading buf (s+STG-1)%STG
        if (s + STG - 1 < S) stage_load(ga, s + STG - 1, spseg, m0, n0, z, sA, sB, tid);
        CP_COMMIT();

        const int buf = s & (STG - 1);
        const uint32_t baseA = smem_u32(sA + buf * A_ST);
        const uint32_t baseB = smem_u32(sB + buf * B_ST);

#pragma unroll
        for (int kk = 0; kk < 2; kk++) {
            uint32_t a[4][4];
            uint32_t b[4][2];
#pragma unroll
            for (int i = 0; i < 4; i++) {
                uint32_t addr = baseA + (uint32_t)(
                    (wm * 64 + i * 16 + (lane & 15)) * LDS_ + kk * 16 + (lane >> 4) * 8) * 2;
                ldsm_x4(a[i][0], a[i][1], a[i][2], a[i][3], addr);
            }
#pragma unroll
            for (int j = 0; j < 2; j++) {
                uint32_t t0, t1, t2, t3;
                uint32_t addr = baseB + (uint32_t)(
                    (wn * 32 + j * 16 + (lane & 7) + ((lane >> 4) & 1) * 8) * LDS_
                    + kk * 16 + ((lane >> 3) & 1) * 8) * 2;
                ldsm_x4(t0, t1, t2, t3, addr);
                b[2 * j][0] = t0; b[2 * j][1] = t1;
                b[2 * j + 1][0] = t2; b[2 * j + 1][1] = t3;
            }
#pragma unroll
            for (int i = 0; i < 4; i++)
#pragma unroll
                for (int j = 0; j < 4; j++) mma16816(acc[i][j], a[i], b[j]);
        }
    }
    CP_WAIT0();

    // ---------------- epilogue (register fragments -> gmem) ----------------
    // acc[i][j]: rows m0+wm*64+i*16+(lane>>2)+{0,8}; cols n0+wn*32+j*8+(lane&3)*2+{0,1}
    const int rbase = m0 + wm * 64 + (lane >> 2);
    const int cbase = n0 + wn * 32 + (lane & 3) * 2;
#pragma unroll
    for (int i = 0; i < 4; i++) {
#pragma unroll
        for (int j = 0; j < 4; j++) {
            const int r = rbase + i * 16;
            const int c = cbase + j * 8;
#pragma unroll
            for (int h = 0; h < 2; h++) {      // h=0: row r, h=1: row r+8
                const int rr = r + h * 8;
                float v0 = acc[i][j][2 * h + 0];
                float v1 = acc[i][j][2 * h + 1];
                if (EPI == EPI_QKV) {
                    const float sc = (c < DD) ? 0.03125f : 1.0f;
                    v0 *= sc; v1 *= sc;
                    half h0 = __float2half_rn(v0);
                    half h1 = __float2half_rn(v1);
                    half l0 = __float2half_rn(v0 - __half2float(h0));
                    half l1 = __float2half_rn(v1 - __half2float(h1));
                    long long o = (long long)rr * NQKV + c;
                    *reinterpret_cast<half2*>(g_qkvh + o) = __halves2half2(h0, h1);
                    *reinterpret_cast<half2*>(g_qkvl + o) = __halves2half2(l0, l1);
                } else if (EPI == EPI_LOGITS) {
                    long long o = ((long long)(z * NS + rr)) * NS + c;
                    *reinterpret_cast<float2*>(g_logits + o) = make_float2(v0, v1);
                } else if (EPI == EPI_SPLIT_Y) {
                    half h0 = __float2half_rn(v0);
                    half h1 = __float2half_rn(v1);
                    half l0 = __float2half_rn(v0 - __half2float(h0));
                    half l1 = __float2half_rn(v1 - __half2float(h1));
                    long long o = ((long long)(z * NS + rr)) * DD + c;
                    *reinterpret_cast<half2*>(g_yh + o) = __halves2half2(h0, h1);
                    *reinterpret_cast<half2*>(g_yl + o) = __halves2half2(l0, l1);
                } else { // EPI_OUT
                    long long o = (long long)rr * DD + c;
                    *reinterpret_cast<float2*>(outp + o) =
                        make_float2(v0 + bias[c], v1 + bias[c + 1]);
                }
            }
        }
    }
}

// ---------------- softmax (per row of logits), writes hi/lo fp16 probs ----------------
__global__ __launch_bounds__(256) void softmax_kernel() {
    const long long row = blockIdx.x;
    const float* __restrict__ L = g_logits + row * (long long)NS;
    const int tid = threadIdx.x;

    float lv[8];
    float mx = -3.4e38f;
#pragma unroll
    for (int i = 0; i < 8; i++) {
        lv[i] = L[tid + i * 256];
        mx = fmaxf(mx, lv[i]);
    }
#pragma unroll
    for (int o = 16; o; o >>= 1) mx = fmaxf(mx, __shfl_xor_sync(0xffffffffu, mx, o));
    __shared__ float smax[8];
    __shared__ float ssum[8];
    if ((tid & 31) == 0) smax[tid >> 5] = mx;
    __syncthreads();
    float bmax = smax[0];
#pragma unroll
    for (int i = 1; i < 8; i++) bmax = fmaxf(bmax, smax[i]);

    float s = 0.0f;
#pragma unroll
    for (int i = 0; i < 8; i++) {
        lv[i] = __expf(lv[i] - bmax);
        s += lv[i];
    }
#pragma unroll
    for (int o = 16; o; o >>= 1) s += __shfl_xor_sync(0xffffffffu, s, o);
    if ((tid & 31) == 0) ssum[tid >> 5] = s;
    __syncthreads();
    float tot = 0.0f;
#pragma unroll
    for (int i = 0; i < 8; i++) tot += ssum[i];
    float inv = 1.0f / tot;

#pragma unroll
    for (int i = 0; i < 8; i++) {
        float p = lv[i] * inv;
        half h = __float2half_rn(p);
        long long o = row * NS + tid + i * 256;
        g_sh[o] = h;
        g_sl[o] = __float2half_rn(p - __half2float(h));
    }
}

// ---------------- launch ----------------
extern "C" void kernel_launch(void* const* d_in, const int* in_sizes, int n_in,
                              void* d_out, int out_size) {
    const float *x = nullptr, *wq = nullptr, *ow = nullptr, *ob = nullptr;
    for (int i = 0; i < n_in; i++) {
        long long sz = in_sizes[i];
        if (sz == (long long)MTOT * DD)      x  = (const float*)d_in[i];
        else if (sz == (long long)DD * NQKV) wq = (const float*)d_in[i];
        else if (sz == (long long)DD * DD)   ow = (const float*)d_in[i];
        else if (sz == DD)                   ob = (const float*)d_in[i];
    }
    if (!x)  x  = (const float*)d_in[0];
    if (!wq) wq = (const float*)d_in[1];
    if (!ow) ow = (const float*)d_in[2];
    if (!ob) ob = (const float*)d_in[3];
    float* out = (float*)d_out;

    cudaFuncSetAttribute(mg_gemm<EPI_QKV>,     cudaFuncAttributeMaxDynamicSharedMemorySize, SMEM_BYTES);
    cudaFuncSetAttribute(mg_gemm<EPI_LOGITS>,  cudaFuncAttributeMaxDynamicSharedMemorySize, SMEM_BYTES);
    cudaFuncSetAttribute(mg_gemm<EPI_SPLIT_Y>, cudaFuncAttributeMaxDynamicSharedMemorySize, SMEM_BYTES);
    cudaFuncSetAttribute(mg_gemm<EPI_OUT>,     cudaFuncAttributeMaxDynamicSharedMemorySize, SMEM_BYTES);

    prep_A<<<(int)(((long long)MTOT * KPQ) / 256), 256>>>(x);
    prep_B<<<(int)(((long long)NQKV * KPQ) / 256), 256>>>(wq);
    prep_OW<<<(DD * DD) / 256, 256>>>(ow);

    // 1) QKV: [16384 x 2048] * [3072 x 2048]^T  -> hi/lo qkv (q pre-scaled)
    {
        GemmArgs ga{};
        ga.nseg = 1; ga.K = KPQ;
        ga.aid[0] = SEG_AP; ga.aoff[0] = 0; ga.az = 0; ga.lda = KPQ;
        ga.bid[0] = SEG_BP; ga.boff[0] = 0; ga.bz = 0; ga.ldb = KPQ;
        mg_gemm<EPI_QKV><<<dim3(NQKV / BN, MTOT / BM, 1), 512, SMEM_BYTES>>>(ga, nullptr, nullptr);
    }
    // 1b) transpose V bands into [z][n][k]
    transpose_v<<<dim3(NS / 32, DD / 32, NB), dim3(32, 8)>>>();
    // 2) QK^T per batch: 3 hi/lo segments -> fp32 logits
    {
        GemmArgs ga{};
        ga.nseg = 3; ga.K = DD; ga.lda = NQKV; ga.ldb = NQKV;
        ga.az = (long long)NS * NQKV; ga.bz = (long long)NS * NQKV;
        ga.aid[0] = SEG_QKVH; ga.aoff[0] = 0; ga.bid[0] = SEG_QKVH; ga.boff[0] = DD;
        ga.aid[1] = SEG_QKVH; ga.aoff[1] = 0; ga.bid[1] = SEG_QKVL; ga.boff[1] = DD;
        ga.aid[2] = SEG_QKVL; ga.aoff[2] = 0; ga.bid[2] = SEG_QKVH; ga.boff[2] = DD;
        mg_gemm<EPI_LOGITS><<<dim3(NS / BN, NS / BM, NB), 512, SMEM_BYTES>>>(ga, nullptr, nullptr);
    }
    // 3) softmax rows -> hi/lo probs
    softmax_kernel<<<MTOT, 256>>>();
    // 4) S*V per batch (NT with V^T): 3 segments -> hi/lo y
    {
        GemmArgs ga{};
        ga.nseg = 3; ga.K = NS; ga.lda = NS; ga.ldb = NS;
        ga.az = (long long)NS * NS; ga.bz = (long long)DD * NS;
        ga.aid[0] = SEG_SH; ga.aoff[0] = 0; ga.bid[0] = SEG_VTH; ga.boff[0] = 0;
        ga.aid[1] = SEG_SH; ga.aoff[1] = 0; ga.bid[1] = SEG_VTL; ga.boff[1] = 0;
        ga.aid[2] = SEG_SL; ga.aoff[2] = 0; ga.bid[2] = SEG_VTH; ga.boff[2] = 0;
        mg_gemm<EPI_SPLIT_Y><<<dim3(DD / BN, NS / BM, NB), 512, SMEM_BYTES>>>(ga, nullptr, nullptr);
    }
    // 5) out = y @ out_w^T + b  (NT): 3 segments -> fp32 output
    {
        GemmArgs ga{};
        ga.nseg = 3; ga.K = DD; ga.lda = DD; ga.ldb = DD; ga.az = 0; ga.bz = 0;
        ga.aid[0] = SEG_YH; ga.aoff[0] = 0; ga.bid[0] = SEG_OWH; ga.boff[0] = 0;
        ga.aid[1] = SEG_YH; ga.aoff[1] = 0; ga.bid[1] = SEG_OWL; ga.boff[1] = 0;
        ga.aid[2] = SEG_YL; ga.aoff[2] = 0; ga.bid[2] = SEG_OWH; ga.boff[2] = 0;
        mg_gemm<EPI_OUT><<<dim3(DD / BN, MTOT / BM, 1), 512, SMEM_BYTES>>>(ga, out, ob);
    }
}

// round 4
// speedup vs baseline: 1.6895x; 1.5960x over previous
#include <cuda_runtime.h>
#include <cuda_fp16.h>
#include <cstdint>

// Problem dims
#define DD    1024
#define NB    8
#define NS    2048
#define MTOT  (NB * NS)        // 16384
#define NQKV  (3 * DD)         // 3072
#define KPQ   2048             // packed K for QKV gemm

// GEMM tiling: block 128x128, 256 threads (8 warps, 2M x 4N), warp 64x32
#define BM 128
#define BN 128
#define BKH 32                 // K halves per stage
#define LDS_ 40                // padded smem stride (halves)
#define TILE_H (BM * LDS_)     // 5120 halves (10240 B) per tile
// gemm1: 4 stages x 2 tiles; gemm3: 2 stages x 4 tiles -> both 81920 B
#define SMEM_BYTES (8 * TILE_H * 2)

// ---------------- scratch (device globals; no runtime allocation) ----------------
__device__ __align__(16) half  g_Ap  [(size_t)MTOT * KPQ];     // packed x operand
__device__ __align__(16) half  g_Bp  [(size_t)NQKV * KPQ];     // packed w operand
__device__ __align__(16) half  g_qkvh[(size_t)MTOT * NQKV];    // hi(qkv), q pre-scaled
__device__ __align__(16) half  g_qkvl[(size_t)MTOT * NQKV];    // lo(qkv)
__device__ __align__(16) float g_logits[(size_t)NB * NS * NS]; // attention logits
__device__ __align__(16) half  g_sh [(size_t)NB * NS * NS];    // hi(softmax)
__device__ __align__(16) half  g_sl [(size_t)NB * NS * NS];    // lo(softmax)
__device__ __align__(16) half  g_yh [(size_t)MTOT * DD];       // hi(y)
__device__ __align__(16) half  g_owh[(size_t)DD * DD];         // hi(out_w)
__device__ __align__(16) half  g_vth[(size_t)NB * DD * NS];    // hi(V^T)  [z][n][k]
__device__ __align__(16) half  g_vtl[(size_t)NB * DD * NS];    // lo(V^T)

enum { SEG_AP = 0, SEG_BP, SEG_QKVH, SEG_QKVL, SEG_SH, SEG_SL, SEG_YH,
       SEG_OWH, SEG_VTH, SEG_VTL };

__device__ __forceinline__ const half* seg_ptr(int id) {
    switch (id) {
        case SEG_AP:   return g_Ap;
        case SEG_BP:   return g_Bp;
        case SEG_QKVH: return g_qkvh;
        case SEG_QKVL: return g_qkvl;
        case SEG_SH:   return g_sh;
        case SEG_SL:   return g_sl;
        case SEG_YH:   return g_yh;
        case SEG_OWH:  return g_owh;
        case SEG_VTH:  return g_vth;
        case SEG_VTL:  return g_vtl;
    }
    return nullptr;
}

// ---------------- PTX helpers ----------------
__device__ __forceinline__ uint32_t smem_u32(const void* p) {
    uint32_t a;
    asm("{ .reg .u64 t; cvta.to.shared.u64 t, %1; cvt.u32.u64 %0, t; }" : "=r"(a) : "l"(p));
    return a;
}

#define CP_ASYNC16(dst, src) \
    asm volatile("cp.async.cg.shared.global [%0], [%1], 16;\n" :: "r"(dst), "l"(src))
#define CP_COMMIT() asm volatile("cp.async.commit_group;\n" ::: "memory")
#define CP_WAIT2()  asm volatile("cp.async.wait_group 2;\n" ::: "memory")
#define CP_WAIT0()  asm volatile("cp.async.wait_group 0;\n" ::: "memory")

__device__ __forceinline__ void ldsm_x4(uint32_t& r0, uint32_t& r1, uint32_t& r2,
                                        uint32_t& r3, uint32_t addr) {
    asm volatile("ldmatrix.sync.aligned.m8n8.x4.shared.b16 {%0,%1,%2,%3}, [%4];"
                 : "=r"(r0), "=r"(r1), "=r"(r2), "=r"(r3) : "r"(addr));
}

__device__ __forceinline__ void mma16816(float* d, const uint32_t* a, const uint32_t* b) {
    asm volatile("mma.sync.aligned.m16n8k16.row.col.f32.f16.f16.f32 "
                 "{%0,%1,%2,%3}, {%4,%5,%6,%7}, {%8,%9}, {%0,%1,%2,%3};"
                 : "+f"(d[0]), "+f"(d[1]), "+f"(d[2]), "+f"(d[3])
                 : "r"(a[0]), "r"(a[1]), "r"(a[2]), "r"(a[3]), "r"(b[0]), "r"(b[1]));
}

// ---------------- hi/lo split helpers ----------------
__device__ __forceinline__ half f_hi(float v) { return __float2half_rn(v); }
__device__ __forceinline__ half f_lo(float v) {
    half h = __float2half_rn(v);
    return __float2half_rn(v - __half2float(h));
}

// K'-mapping for the packed QKV GEMM.
// Reference splits contraction dim 1024 into [0,256) fp16 | [256,768) fp32 | [768,1024) fp16.
__device__ __forceinline__ void map_k(int kp, int& src, bool& alo, bool& blo) {
    alo = false; blo = false;
    if (kp < 256)        { src = kp; }
    else if (kp < 512)   { src = 768 + (kp - 256); }
    else if (kp < 1024)  { src = 256 + (kp - 512); }
    else if (kp < 1536)  { src = 256 + (kp - 1024); blo = true; }
    else                 { src = 256 + (kp - 1536); alo = true; }
}

// ---------------- prep kernels ----------------
__global__ void prep_A(const float* __restrict__ x) {
    long long idx = (long long)blockIdx.x * blockDim.x + threadIdx.x;
    if (idx >= (long long)MTOT * KPQ) return;
    int kp = (int)(idx & (KPQ - 1));
    long long m = idx >> 11;
    int src; bool alo, blo;
    map_k(kp, src, alo, blo);
    float v = x[m * DD + src];
    g_Ap[idx] = alo ? f_lo(v) : f_hi(v);
}

__global__ void prep_B(const float* __restrict__ w) {
    long long idx = (long long)blockIdx.x * blockDim.x + threadIdx.x;
    if (idx >= (long long)NQKV * KPQ) return;
    int kp = (int)(idx & (KPQ - 1));
    int n  = (int)(idx >> 11);
    int src; bool alo, blo;
    map_k(kp, src, alo, blo);
    float v = w[(long long)src * NQKV + n];
    g_Bp[idx] = blo ? f_lo(v) : f_hi(v);
}

__global__ void prep_OW(const float* __restrict__ ow) {
    int idx = blockIdx.x * blockDim.x + threadIdx.x;
    if (idx >= DD * DD) return;
    g_owh[idx] = f_hi(ow[idx]);
}

// V transpose: g_qkv{h,l}[z][k][2*DD + n] -> g_vt{h,l}[z][n][k]
__global__ void transpose_v() {
    __shared__ half th[32][33];
    __shared__ half tl[32][33];
    const int z  = blockIdx.z;
    const int k0 = blockIdx.x * 32;
    const int n0 = blockIdx.y * 32;
    const int tx = threadIdx.x;
    const int ty = threadIdx.y;
#pragma unroll
    for (int i = 0; i < 32; i += 8) {
        long long src = ((long long)(z * NS + k0 + ty + i)) * NQKV + 2 * DD + n0 + tx;
        th[ty + i][tx] = g_qkvh[src];
        tl[ty + i][tx] = g_qkvl[src];
    }
    __syncthreads();
#pragma unroll
    for (int i = 0; i < 32; i += 8) {
        long long dst = ((long long)(z * DD + n0 + ty + i)) * NS + k0 + tx;
        g_vth[dst] = th[tx][ty + i];
        g_vtl[dst] = tl[tx][ty + i];
    }
}

// ---------------- GEMM args ----------------
struct G1 { long long aoff, boff, az, bz; int aid, bid, lda, ldb, K; };
struct G3 { long long aoff, boff, az, bz; int aidh, aidl, bidh, bidl, lda, ldb, K; };

enum { EPI_QKV = 0, EPI_OUT = 1, EPI_LOGITS = 2, EPI_YHI = 3 };

// shared epilogue: acc[i][j] rows m0+wm*64+i*16+(lane>>2)+{0,8},
// cols n0+wn*32+j*8+(lane&3)*2+{0,1}
template <int EPI>
__device__ __forceinline__ void epilogue(float acc[4][4][4], int m0, int n0, int z,
                                         int wm, int wn, int lane,
                                         float* __restrict__ outp,
                                         const float* __restrict__ bias) {
    const int rbase = m0 + wm * 64 + (lane >> 2);
    const int cbase = n0 + wn * 32 + (lane & 3) * 2;
#pragma unroll
    for (int i = 0; i < 4; i++) {
#pragma unroll
        for (int j = 0; j < 4; j++) {
            const int c = cbase + j * 8;
#pragma unroll
            for (int h = 0; h < 2; h++) {
                const int rr = rbase + i * 16 + h * 8;
                float v0 = acc[i][j][2 * h + 0];
                float v1 = acc[i][j][2 * h + 1];
                if (EPI == EPI_QKV) {
                    const float sc = (c < DD) ? 0.03125f : 1.0f;
                    v0 *= sc; v1 *= sc;
                    half h0 = __float2half_rn(v0);
                    half h1 = __float2half_rn(v1);
                    half l0 = __float2half_rn(v0 - __half2float(h0));
                    half l1 = __float2half_rn(v1 - __half2float(h1));
                    long long o = (long long)rr * NQKV + c;
                    *reinterpret_cast<half2*>(g_qkvh + o) = __halves2half2(h0, h1);
                    *reinterpret_cast<half2*>(g_qkvl + o) = __halves2half2(l0, l1);
                } else if (EPI == EPI_OUT) {
                    long long o = (long long)rr * DD + c;
                    *reinterpret_cast<float2*>(outp + o) =
                        make_float2(v0 + bias[c], v1 + bias[c + 1]);
                } else if (EPI == EPI_LOGITS) {
                    long long o = ((long long)(z * NS + rr)) * NS + c;
                    *reinterpret_cast<float2*>(g_logits + o) = make_float2(v0, v1);
                } else { // EPI_YHI
                    long long o = ((long long)(z * NS + rr)) * DD + c;
                    *reinterpret_cast<half2*>(g_yh + o) =
                        __halves2half2(__float2half_rn(v0), __float2half_rn(v1));
                }
            }
        }
    }
}

// ---------------- single-pair GEMM (QKV, out-proj): 4 stages ----------------
__device__ __forceinline__ void g1_load(const G1& g, int s, int m0, int n0, int z,
                                        uint32_t smb, int tid) {
    const int k0 = s * BKH;
    const half* A = seg_ptr(g.aid) + (long long)z * g.az + g.aoff;
    const half* B = seg_ptr(g.bid) + (long long)z * g.bz + g.boff;
    const uint32_t sa = smb + (uint32_t)((s & 3) * 2 + 0) * (TILE_H * 2);
    const uint32_t sb = smb + (uint32_t)((s & 3) * 2 + 1) * (TILE_H * 2);
#pragma unroll
    for (int i = 0; i < 2; i++) {
        int c = tid + i * 256;
        int r = c >> 2;
        int kc = (c & 3) * 8;
        CP_ASYNC16(sa + (uint32_t)(r * LDS_ + kc) * 2, A + (long long)(m0 + r) * g.lda + k0 + kc);
        CP_ASYNC16(sb + (uint32_t)(r * LDS_ + kc) * 2, B + (long long)(n0 + r) * g.ldb + k0 + kc);
    }
}

template <int EPI>
__global__ __launch_bounds__(256, 2) void mg_gemm1(G1 g, float* __restrict__ outp,
                                                   const float* __restrict__ bias) {
    extern __shared__ half sm[];
    const uint32_t smb = smem_u32(sm);
    const int tid  = threadIdx.x;
    const int lane = tid & 31;
    const int wm = (tid >> 5) >> 2;    // 0..1
    const int wn = (tid >> 5) & 3;     // 0..3
    const int m0 = blockIdx.y * BM;
    const int n0 = blockIdx.x * BN;
    const int z  = blockIdx.z;

    float acc[4][4][4];
#pragma unroll
    for (int i = 0; i < 4; i++)
#pragma unroll
        for (int j = 0; j < 4; j++)
#pragma unroll
            for (int e = 0; e < 4; e++) acc[i][j][e] = 0.0f;

    const int S = g.K / BKH;
#pragma unroll
    for (int p = 0; p < 3; p++) { g1_load(g, p, m0, n0, z, smb, tid); CP_COMMIT(); }

    for (int s = 0; s < S; s++) {
        CP_WAIT2();
        __syncthreads();
        if (s + 3 < S) g1_load(g, s + 3, m0, n0, z, smb, tid);
        CP_COMMIT();

        const uint32_t baseA = smb + (uint32_t)((s & 3) * 2 + 0) * (TILE_H * 2);
        const uint32_t baseB = smb + (uint32_t)((s & 3) * 2 + 1) * (TILE_H * 2);
#pragma unroll
        for (int kk = 0; kk < 2; kk++) {
            uint32_t a[4][4];
#pragma unroll
            for (int i = 0; i < 4; i++) {
                uint32_t addr = baseA + (uint32_t)(
                    (wm * 64 + i * 16 + (lane & 15)) * LDS_ + kk * 16 + (lane >> 4) * 8) * 2;
                ldsm_x4(a[i][0], a[i][1], a[i][2], a[i][3], addr);
            }
#pragma unroll
            for (int j2 = 0; j2 < 2; j2++) {
                uint32_t b[2][2];
                uint32_t t0, t1, t2, t3;
                uint32_t addr = baseB + (uint32_t)(
                    (wn * 32 + j2 * 16 + (lane & 7) + ((lane >> 4) & 1) * 8) * LDS_
                    + kk * 16 + ((lane >> 3) & 1) * 8) * 2;
                ldsm_x4(t0, t1, t2, t3, addr);
                b[0][0] = t0; b[0][1] = t1; b[1][0] = t2; b[1][1] = t3;
#pragma unroll
                for (int jj = 0; jj < 2; jj++)
#pragma unroll
                    for (int i = 0; i < 4; i++) mma16816(acc[i][2 * j2 + jj], a[i], b[jj]);
            }
        }
    }
    CP_WAIT0();
    epilogue<EPI>(acc, m0, n0, z, wm, wn, lane, outp, bias);
}

// ---------------- fused 3-segment GEMM (logits, SV): 2 stages ----------------
// acc += Ah*Bh + Ah*Bl + Al*Bh
__device__ __forceinline__ void g3_load(const G3& g, int s, int m0, int n0, int z,
                                        uint32_t smb, int tid) {
    const int k0 = s * BKH;
    const half* Ah = seg_ptr(g.aidh) + (long long)z * g.az + g.aoff;
    const half* Al = seg_ptr(g.aidl) + (long long)z * g.az + g.aoff;
    const half* Bh = seg_ptr(g.bidh) + (long long)z * g.bz + g.boff;
    const half* Bl = seg_ptr(g.bidl) + (long long)z * g.bz + g.boff;
    const uint32_t sb0 = smb + (uint32_t)(s & 1) * 4 * (TILE_H * 2);
#pragma unroll
    for (int i = 0; i < 2; i++) {
        int c = tid + i * 256;
        int r = c >> 2;
        int kc = (c & 3) * 8;
        uint32_t d = sb0 + (uint32_t)(r * LDS_ + kc) * 2;
        long long ao = (long long)(m0 + r) * g.lda + k0 + kc;
        long long bo = (long long)(n0 + r) * g.ldb + k0 + kc;
        CP_ASYNC16(d + 0 * (TILE_H * 2), Ah + ao);
        CP_ASYNC16(d + 1 * (TILE_H * 2), Al + ao);
        CP_ASYNC16(d + 2 * (TILE_H * 2), Bh + bo);
        CP_ASYNC16(d + 3 * (TILE_H * 2), Bl + bo);
    }
}

template <int EPI>
__global__ __launch_bounds__(256, 2) void mg_gemm3(G3 g, float* __restrict__ outp,
                                                   const float* __restrict__ bias) {
    extern __shared__ half sm[];
    const uint32_t smb = smem_u32(sm);
    const int tid  = threadIdx.x;
    const int lane = tid & 31;
    const int wm = (tid >> 5) >> 2;
    const int wn = (tid >> 5) & 3;
    const int m0 = blockIdx.y * BM;
    const int n0 = blockIdx.x * BN;
    const int z  = blockIdx.z;

    float acc[4][4][4];
#pragma unroll
    for (int i = 0; i < 4; i++)
#pragma unroll
        for (int j = 0; j < 4; j++)
#pragma unroll
            for (int e = 0; e < 4; e++) acc[i][j][e] = 0.0f;

    const int S = g.K / BKH;
    g3_load(g, 0, m0, n0, z, smb, tid);
    CP_COMMIT();

    for (int s = 0; s < S; s++) {
        CP_WAIT0();
        __syncthreads();
        if (s + 1 < S) g3_load(g, s + 1, m0, n0, z, smb, tid);
        CP_COMMIT();

        const uint32_t sb0 = smb + (uint32_t)(s & 1) * 4 * (TILE_H * 2);
        const uint32_t baseAh = sb0;
        const uint32_t baseAl = sb0 + 1 * (TILE_H * 2);
        const uint32_t baseBh = sb0 + 2 * (TILE_H * 2);
        const uint32_t baseBl = sb0 + 3 * (TILE_H * 2);
#pragma unroll
        for (int kk = 0; kk < 2; kk++) {
            uint32_t ah[4][4], al[4][4];
#pragma unroll
            for (int i = 0; i < 4; i++) {
                uint32_t ao = (uint32_t)(
                    (wm * 64 + i * 16 + (lane & 15)) * LDS_ + kk * 16 + (lane >> 4) * 8) * 2;
                ldsm_x4(ah[i][0], ah[i][1], ah[i][2], ah[i][3], baseAh + ao);
                ldsm_x4(al[i][0], al[i][1], al[i][2], al[i][3], baseAl + ao);
            }
#pragma unroll
            for (int j2 = 0; j2 < 2; j2++) {
                uint32_t bo = (uint32_t)(
                    (wn * 32 + j2 * 16 + (lane & 7) + ((lane >> 4) & 1) * 8) * LDS_
                    + kk * 16 + ((lane >> 3) & 1) * 8) * 2;
                uint32_t bh[2][2], bl[2][2];
                {
                    uint32_t t0, t1, t2, t3;
                    ldsm_x4(t0, t1, t2, t3, baseBh + bo);
                    bh[0][0] = t0; bh[0][1] = t1; bh[1][0] = t2; bh[1][1] = t3;
                    ldsm_x4(t0, t1, t2, t3, baseBl + bo);
                    bl[0][0] = t0; bl[0][1] = t1; bl[1][0] = t2; bl[1][1] = t3;
                }
#pragma unroll
                for (int jj = 0; jj < 2; jj++) {
                    const int j = 2 * j2 + jj;
#pragma unroll
                    for (int i = 0; i < 4; i++) mma16816(acc[i][j], ah[i], bh[jj]);
#pragma unroll
                    for (int i = 0; i < 4; i++) mma16816(acc[i][j], ah[i], bl[jj]);
#pragma unroll
                    for (int i = 0; i < 4; i++) mma16816(acc[i][j], al[i], bh[jj]);
                }
            }
        }
    }
    CP_WAIT0();
    epilogue<EPI>(acc, m0, n0, z, wm, wn, lane, outp, bias);
}

// ---------------- softmax (per row of logits), writes hi/lo fp16 probs ----------------
__global__ __launch_bounds__(256) void softmax_kernel() {
    const long long row = blockIdx.x;
    const float* __restrict__ L = g_logits + row * (long long)NS;
    const int tid = threadIdx.x;

    float lv[8];
    float mx = -3.4e38f;
#pragma unroll
    for (int i = 0; i < 8; i++) {
        lv[i] = L[tid + i * 256];
        mx = fmaxf(mx, lv[i]);
    }
#pragma unroll
    for (int o = 16; o; o >>= 1) mx = fmaxf(mx, __shfl_xor_sync(0xffffffffu, mx, o));
    __shared__ float smax[8];
    __shared__ float ssum[8];
    if ((tid & 31) == 0) smax[tid >> 5] = mx;
    __syncthreads();
    float bmax = smax[0];
#pragma unroll
    for (int i = 1; i < 8; i++) bmax = fmaxf(bmax, smax[i]);

    float s = 0.0f;
#pragma unroll
    for (int i = 0; i < 8; i++) {
        lv[i] = __expf(lv[i] - bmax);
        s += lv[i];
    }
#pragma unroll
    for (int o = 16; o; o >>= 1) s += __shfl_xor_sync(0xffffffffu, s, o);
    if ((tid & 31) == 0) ssum[tid >> 5] = s;
    __syncthreads();
    float tot = 0.0f;
#pragma unroll
    for (int i = 0; i < 8; i++) tot += ssum[i];
    float inv = 1.0f / tot;

#pragma unroll
    for (int i = 0; i < 8; i++) {
        float p = lv[i] * inv;
        half h = __float2half_rn(p);
        long long o = row * NS + tid + i * 256;
        g_sh[o] = h;
        g_sl[o] = __float2half_rn(p - __half2float(h));
    }
}

// ---------------- launch ----------------
extern "C" void kernel_launch(void* const* d_in, const int* in_sizes, int n_in,
                              void* d_out, int out_size) {
    const float *x = nullptr, *wq = nullptr, *ow = nullptr, *ob = nullptr;
    for (int i = 0; i < n_in; i++) {
        long long sz = in_sizes[i];
        if (sz == (long long)MTOT * DD)      x  = (const float*)d_in[i];
        else if (sz == (long long)DD * NQKV) wq = (const float*)d_in[i];
        else if (sz == (long long)DD * DD)   ow = (const float*)d_in[i];
        else if (sz == DD)                   ob = (const float*)d_in[i];
    }
    if (!x)  x  = (const float*)d_in[0];
    if (!wq) wq = (const float*)d_in[1];
    if (!ow) ow = (const float*)d_in[2];
    if (!ob) ob = (const float*)d_in[3];
    float* out = (float*)d_out;

    cudaFuncSetAttribute(mg_gemm1<EPI_QKV>,    cudaFuncAttributeMaxDynamicSharedMemorySize, SMEM_BYTES);
    cudaFuncSetAttribute(mg_gemm1<EPI_OUT>,    cudaFuncAttributeMaxDynamicSharedMemorySize, SMEM_BYTES);
    cudaFuncSetAttribute(mg_gemm3<EPI_LOGITS>, cudaFuncAttributeMaxDynamicSharedMemorySize, SMEM_BYTES);
    cudaFuncSetAttribute(mg_gemm3<EPI_YHI>,    cudaFuncAttributeMaxDynamicSharedMemorySize, SMEM_BYTES);

    prep_A<<<(int)(((long long)MTOT * KPQ) / 256), 256>>>(x);
    prep_B<<<(int)(((long long)NQKV * KPQ) / 256), 256>>>(wq);
    prep_OW<<<(DD * DD) / 256, 256>>>(ow);

    // 1) QKV: [16384 x 2048] * [3072 x 2048]^T -> hi/lo qkv (q pre-scaled)
    {
        G1 g{};
        g.aid = SEG_AP; g.aoff = 0; g.az = 0; g.lda = KPQ;
        g.bid = SEG_BP; g.boff = 0; g.bz = 0; g.ldb = KPQ;
        g.K = KPQ;
        mg_gemm1<EPI_QKV><<<dim3(NQKV / BN, MTOT / BM, 1), 256, SMEM_BYTES>>>(g, nullptr, nullptr);
    }
    // 1b) transpose V bands into [z][n][k]
    transpose_v<<<dim3(NS / 32, DD / 32, NB), dim3(32, 8)>>>();
    // 2) QK^T per batch, fused 3-term -> fp32 logits
    {
        G3 g{};
        g.aidh = SEG_QKVH; g.aidl = SEG_QKVL; g.aoff = 0;
        g.bidh = SEG_QKVH; g.bidl = SEG_QKVL; g.boff = DD;
        g.lda = NQKV; g.ldb = NQKV;
        g.az = (long long)NS * NQKV; g.bz = (long long)NS * NQKV;
        g.K = DD;
        mg_gemm3<EPI_LOGITS><<<dim3(NS / BN, NS / BM, NB), 256, SMEM_BYTES>>>(g, nullptr, nullptr);
    }
    // 3) softmax rows -> hi/lo probs
    softmax_kernel<<<MTOT, 256>>>();
    // 4) S*V per batch, fused 3-term -> hi(y) only
    {
        G3 g{};
        g.aidh = SEG_SH;  g.aidl = SEG_SL;  g.aoff = 0;
        g.bidh = SEG_VTH; g.bidl = SEG_VTL; g.boff = 0;
        g.lda = NS; g.ldb = NS;
        g.az = (long long)NS * NS; g.bz = (long long)DD * NS;
        g.K = NS;
        mg_gemm3<EPI_YHI><<<dim3(DD / BN, NS / BM, NB), 256, SMEM_BYTES>>>(g, nullptr, nullptr);
    }
    // 5) out = yh @ owh^T + b (single fp16 term)
    {
        G1 g{};
        g.aid = SEG_YH;  g.aoff = 0; g.az = 0; g.lda = DD;
        g.bid = SEG_OWH; g.boff = 0; g.bz = 0; g.ldb = DD;
        g.K = DD;
        mg_gemm1<EPI_OUT><<<dim3(DD / BN, MTOT / BM, 1), 256, SMEM_BYTES>>>(g, out, ob);
    }
}

// round 5
// speedup vs baseline: 2.2396x; 1.3256x over previous
#include <cuda_runtime.h>
#include <cuda_fp16.h>
#include <cstdint>

// Problem dims
#define DD    1024
#define NB    8
#define NS    2048
#define MTOT  (NB * NS)        // 16384
#define NQKV  (3 * DD)         // 3072
#define KPQ   1536             // packed K for QKV gemm (A all-hi; B: 1024 hi + 512 mid-lo)

// GEMM tiling: block 128x128, 256 threads (8 warps, 2M x 4N), warp 64x32
#define BM 128
#define BN 128
#define BKH 32                 // K halves per stage
#define LDS_ 40                // padded smem stride (halves)
#define TILE_H (BM * LDS_)     // 5120 halves (10240 B) per tile
#define TILE_B (TILE_H * 2)
#define SMEM_G1 (8 * TILE_B)   // 4 stages x 2 tiles = 81920 B
#define SMEM_G2 (9 * TILE_B)   // 3 stages x 3 tiles = 92160 B

// ---------------- scratch (device globals; no runtime allocation) ----------------
__device__ __align__(16) half  g_Ap  [(size_t)MTOT * KPQ];     // packed x operand (all hi)
__device__ __align__(16) half  g_Bp  [(size_t)NQKV * KPQ];     // packed w operand
__device__ __align__(16) half  g_qkvh[(size_t)MTOT * NQKV];    // hi(qkv), q pre-scaled
__device__ __align__(16) half  g_qkvl[(size_t)MTOT * NQKV];    // lo(qkv) (k,v bands used)
__device__ __align__(16) float g_logits[(size_t)NB * NS * NS]; // attention logits
__device__ __align__(16) half  g_sh [(size_t)NB * NS * NS];    // hi(softmax)
__device__ __align__(16) half  g_yh [(size_t)MTOT * DD];       // hi(y)
__device__ __align__(16) half  g_owh[(size_t)DD * DD];         // hi(out_w)
__device__ __align__(16) half  g_vth[(size_t)NB * DD * NS];    // hi(V^T)  [z][n][k]
__device__ __align__(16) half  g_vtl[(size_t)NB * DD * NS];    // lo(V^T)

enum { SEG_AP = 0, SEG_BP, SEG_QKVH, SEG_QKVL, SEG_SH, SEG_YH,
       SEG_OWH, SEG_VTH, SEG_VTL };

__device__ __forceinline__ const half* seg_ptr(int id) {
    switch (id) {
        case SEG_AP:   return g_Ap;
        case SEG_BP:   return g_Bp;
        case SEG_QKVH: return g_qkvh;
        case SEG_QKVL: return g_qkvl;
        case SEG_SH:   return g_sh;
        case SEG_YH:   return g_yh;
        case SEG_OWH:  return g_owh;
        case SEG_VTH:  return g_vth;
        case SEG_VTL:  return g_vtl;
    }
    return nullptr;
}

// ---------------- PTX helpers ----------------
__device__ __forceinline__ uint32_t smem_u32(const void* p) {
    uint32_t a;
    asm("{ .reg .u64 t; cvta.to.shared.u64 t, %1; cvt.u32.u64 %0, t; }" : "=r"(a) : "l"(p));
    return a;
}

#define CP_ASYNC16(dst, src) \
    asm volatile("cp.async.cg.shared.global [%0], [%1], 16;\n" :: "r"(dst), "l"(src))
#define CP_COMMIT() asm volatile("cp.async.commit_group;\n" ::: "memory")
#define CP_WAIT1()  asm volatile("cp.async.wait_group 1;\n" ::: "memory")
#define CP_WAIT2()  asm volatile("cp.async.wait_group 2;\n" ::: "memory")
#define CP_WAIT0()  asm volatile("cp.async.wait_group 0;\n" ::: "memory")

__device__ __forceinline__ void ldsm_x4(uint32_t& r0, uint32_t& r1, uint32_t& r2,
                                        uint32_t& r3, uint32_t addr) {
    asm volatile("ldmatrix.sync.aligned.m8n8.x4.shared.b16 {%0,%1,%2,%3}, [%4];"
                 : "=r"(r0), "=r"(r1), "=r"(r2), "=r"(r3) : "r"(addr));
}

__device__ __forceinline__ void mma16816(float* d, const uint32_t* a, const uint32_t* b) {
    asm volatile("mma.sync.aligned.m16n8k16.row.col.f32.f16.f16.f32 "
                 "{%0,%1,%2,%3}, {%4,%5,%6,%7}, {%8,%9}, {%0,%1,%2,%3};"
                 : "+f"(d[0]), "+f"(d[1]), "+f"(d[2]), "+f"(d[3])
                 : "r"(a[0]), "r"(a[1]), "r"(a[2]), "r"(a[3]), "r"(b[0]), "r"(b[1]));
}

// ---------------- hi/lo split helpers ----------------
__device__ __forceinline__ half f_hi(float v) { return __float2half_rn(v); }
__device__ __forceinline__ half f_lo(float v) {
    half h = __float2half_rn(v);
    return __float2half_rn(v - __half2float(h));
}

// K'-mapping for the packed QKV GEMM (KPQ=1536).
// k' in [0,256)    : low band 1 [0,256),      hi . hi
// k' in [256,512)  : low band 2 [768,1024),   hi . hi
// k' in [512,1024) : middle [256,768),        hi . hi
// k' in [1024,1536): middle [256,768),        hi(A) . lo(B)
__device__ __forceinline__ int map_src(int kp, bool& blo) {
    blo = false;
    if (kp < 256)        return kp;
    if (kp < 512)        return 768 + (kp - 256);
    if (kp < 1024)       return 256 + (kp - 512);
    blo = true;          return 256 + (kp - 1024);
}

// ---------------- prep kernels ----------------
__global__ void prep_A(const float* __restrict__ x) {
    long long idx = (long long)blockIdx.x * blockDim.x + threadIdx.x;
    if (idx >= (long long)MTOT * KPQ) return;
    int kp = (int)(idx % KPQ);
    long long m = idx / KPQ;
    bool blo;
    int src = map_src(kp, blo);
    g_Ap[idx] = f_hi(x[m * DD + src]);
}

__global__ void prep_B(const float* __restrict__ w) {
    long long idx = (long long)blockIdx.x * blockDim.x + threadIdx.x;
    if (idx >= (long long)NQKV * KPQ) return;
    int kp = (int)(idx % KPQ);
    int n  = (int)(idx / KPQ);
    bool blo;
    int src = map_src(kp, blo);
    float v = w[(long long)src * NQKV + n];
    g_Bp[idx] = blo ? f_lo(v) : f_hi(v);
}

__global__ void prep_OW(const float* __restrict__ ow) {
    int idx = blockIdx.x * blockDim.x + threadIdx.x;
    if (idx >= DD * DD) return;
    g_owh[idx] = f_hi(ow[idx]);
}

// V transpose: g_qkv{h,l}[z][k][2*DD + n] -> g_vt{h,l}[z][n][k]
__global__ void transpose_v() {
    __shared__ half th[32][33];
    __shared__ half tl[32][33];
    const int z  = blockIdx.z;
    const int k0 = blockIdx.x * 32;
    const int n0 = blockIdx.y * 32;
    const int tx = threadIdx.x;
    const int ty = threadIdx.y;
#pragma unroll
    for (int i = 0; i < 32; i += 8) {
        long long src = ((long long)(z * NS + k0 + ty + i)) * NQKV + 2 * DD + n0 + tx;
        th[ty + i][tx] = g_qkvh[src];
        tl[ty + i][tx] = g_qkvl[src];
    }
    __syncthreads();
#pragma unroll
    for (int i = 0; i < 32; i += 8) {
        long long dst = ((long long)(z * DD + n0 + ty + i)) * NS + k0 + tx;
        g_vth[dst] = th[tx][ty + i];
        g_vtl[dst] = tl[tx][ty + i];
    }
}

// ---------------- GEMM args ----------------
struct G1 { long long aoff, boff, az, bz; int aid, bid, lda, ldb, K; };
struct G2 { long long aoff, boff, az, bz; int aid, bidh, bidl, lda, ldb, K; };

enum { EPI_QKV = 0, EPI_OUT = 1, EPI_LOGITS = 2, EPI_YHI = 3 };

// shared epilogue: acc[i][j] rows m0+wm*64+i*16+(lane>>2)+{0,8},
// cols n0+wn*32+j*8+(lane&3)*2+{0,1}
template <int EPI>
__device__ __forceinline__ void epilogue(float acc[4][4][4], int m0, int n0, int z,
                                         int wm, int wn, int lane,
                                         float* __restrict__ outp,
                                         const float* __restrict__ bias) {
    const int rbase = m0 + wm * 64 + (lane >> 2);
    const int cbase = n0 + wn * 32 + (lane & 3) * 2;
#pragma unroll
    for (int i = 0; i < 4; i++) {
#pragma unroll
        for (int j = 0; j < 4; j++) {
            const int c = cbase + j * 8;
#pragma unroll
            for (int h = 0; h < 2; h++) {
                const int rr = rbase + i * 16 + h * 8;
                float v0 = acc[i][j][2 * h + 0];
                float v1 = acc[i][j][2 * h + 1];
                if (EPI == EPI_QKV) {
                    const float sc = (c < DD) ? 0.03125f : 1.0f;
                    v0 *= sc; v1 *= sc;
                    half h0 = __float2half_rn(v0);
                    half h1 = __float2half_rn(v1);
                    long long o = (long long)rr * NQKV + c;
                    *reinterpret_cast<half2*>(g_qkvh + o) = __halves2half2(h0, h1);
                    if (c >= DD) {  // q-lo never consumed
                        half l0 = __float2half_rn(v0 - __half2float(h0));
                        half l1 = __float2half_rn(v1 - __half2float(h1));
                        *reinterpret_cast<half2*>(g_qkvl + o) = __halves2half2(l0, l1);
                    }
                } else if (EPI == EPI_OUT) {
                    long long o = (long long)rr * DD + c;
                    *reinterpret_cast<float2*>(outp + o) =
                        make_float2(v0 + bias[c], v1 + bias[c + 1]);
                } else if (EPI == EPI_LOGITS) {
                    long long o = ((long long)(z * NS + rr)) * NS + c;
                    *reinterpret_cast<float2*>(g_logits + o) = make_float2(v0, v1);
                } else { // EPI_YHI
                    long long o = ((long long)(z * NS + rr)) * DD + c;
                    *reinterpret_cast<half2*>(g_yh + o) =
                        __halves2half2(__float2half_rn(v0), __float2half_rn(v1));
                }
            }
        }
    }
}

// ---------------- single-pair GEMM (QKV, out-proj): 4 stages x 2 tiles ----------------
__device__ __forceinline__ void g1_load(const G1& g, int s, int m0, int n0, int z,
                                        uint32_t smb, int tid) {
    const int k0 = s * BKH;
    const half* A = seg_ptr(g.aid) + (long long)z * g.az + g.aoff;
    const half* B = seg_ptr(g.bid) + (long long)z * g.bz + g.boff;
    const uint32_t sa = smb + (uint32_t)((s & 3) * 2 + 0) * TILE_B;
    const uint32_t sb = smb + (uint32_t)((s & 3) * 2 + 1) * TILE_B;
#pragma unroll
    for (int i = 0; i < 2; i++) {
        int c = tid + i * 256;
        int r = c >> 2;
        int kc = (c & 3) * 8;
        CP_ASYNC16(sa + (uint32_t)(r * LDS_ + kc) * 2, A + (long long)(m0 + r) * g.lda + k0 + kc);
        CP_ASYNC16(sb + (uint32_t)(r * LDS_ + kc) * 2, B + (long long)(n0 + r) * g.ldb + k0 + kc);
    }
}

template <int EPI>
__global__ __launch_bounds__(256, 2) void mg_gemm1(G1 g, float* __restrict__ outp,
                                                   const float* __restrict__ bias) {
    extern __shared__ half sm[];
    const uint32_t smb = smem_u32(sm);
    const int tid  = threadIdx.x;
    const int lane = tid & 31;
    const int wm = (tid >> 5) >> 2;    // 0..1
    const int wn = (tid >> 5) & 3;     // 0..3
    const int m0 = blockIdx.y * BM;
    const int n0 = blockIdx.x * BN;
    const int z  = blockIdx.z;

    float acc[4][4][4];
#pragma unroll
    for (int i = 0; i < 4; i++)
#pragma unroll
        for (int j = 0; j < 4; j++)
#pragma unroll
            for (int e = 0; e < 4; e++) acc[i][j][e] = 0.0f;

    const int S = g.K / BKH;
#pragma unroll
    for (int p = 0; p < 3; p++) { g1_load(g, p, m0, n0, z, smb, tid); CP_COMMIT(); }

    for (int s = 0; s < S; s++) {
        CP_WAIT2();
        __syncthreads();
        if (s + 3 < S) g1_load(g, s + 3, m0, n0, z, smb, tid);
        CP_COMMIT();

        const uint32_t baseA = smb + (uint32_t)((s & 3) * 2 + 0) * TILE_B;
        const uint32_t baseB = smb + (uint32_t)((s & 3) * 2 + 1) * TILE_B;
#pragma unroll
        for (int kk = 0; kk < 2; kk++) {
            uint32_t a[4][4];
#pragma unroll
            for (int i = 0; i < 4; i++) {
                uint32_t addr = baseA + (uint32_t)(
                    (wm * 64 + i * 16 + (lane & 15)) * LDS_ + kk * 16 + (lane >> 4) * 8) * 2;
                ldsm_x4(a[i][0], a[i][1], a[i][2], a[i][3], addr);
            }
#pragma unroll
            for (int j2 = 0; j2 < 2; j2++) {
                uint32_t b[2][2];
                uint32_t t0, t1, t2, t3;
                uint32_t addr = baseB + (uint32_t)(
                    (wn * 32 + j2 * 16 + (lane & 7) + ((lane >> 4) & 1) * 8) * LDS_
                    + kk * 16 + ((lane >> 3) & 1) * 8) * 2;
                ldsm_x4(t0, t1, t2, t3, addr);
                b[0][0] = t0; b[0][1] = t1; b[1][0] = t2; b[1][1] = t3;
#pragma unroll
                for (int jj = 0; jj < 2; jj++)
#pragma unroll
                    for (int i = 0; i < 4; i++) mma16816(acc[i][2 * j2 + jj], a[i], b[jj]);
            }
        }
    }
    CP_WAIT0();
    epilogue<EPI>(acc, m0, n0, z, wm, wn, lane, outp, bias);
}

// ---------------- fused 2-term GEMM (logits, SV): acc += Ah*Bh + Ah*Bl ----------------
// 3 stages x 3 tiles (A, Bh, Bl)
__device__ __forceinline__ void g2_load(const G2& g, int s, int m0, int n0, int z,
                                        uint32_t smb, int tid) {
    const int k0 = s * BKH;
    const half* A  = seg_ptr(g.aid)  + (long long)z * g.az + g.aoff;
    const half* Bh = seg_ptr(g.bidh) + (long long)z * g.bz + g.boff;
    const half* Bl = seg_ptr(g.bidl) + (long long)z * g.bz + g.boff;
    int buf = s % 3;
    const uint32_t sb0 = smb + (uint32_t)(buf * 3) * TILE_B;
#pragma unroll
    for (int i = 0; i < 2; i++) {
        int c = tid + i * 256;
        int r = c >> 2;
        int kc = (c & 3) * 8;
        uint32_t d = sb0 + (uint32_t)(r * LDS_ + kc) * 2;
        long long ao = (long long)(m0 + r) * g.lda + k0 + kc;
        long long bo = (long long)(n0 + r) * g.ldb + k0 + kc;
        CP_ASYNC16(d + 0 * TILE_B, A  + ao);
        CP_ASYNC16(d + 1 * TILE_B, Bh + bo);
        CP_ASYNC16(d + 2 * TILE_B, Bl + bo);
    }
}

template <int EPI>
__global__ __launch_bounds__(256, 2) void mg_gemm2(G2 g, float* __restrict__ outp,
                                                   const float* __restrict__ bias) {
    extern __shared__ half sm[];
    const uint32_t smb = smem_u32(sm);
    const int tid  = threadIdx.x;
    const int lane = tid & 31;
    const int wm = (tid >> 5) >> 2;
    const int wn = (tid >> 5) & 3;
    const int m0 = blockIdx.y * BM;
    const int n0 = blockIdx.x * BN;
    const int z  = blockIdx.z;

    float acc[4][4][4];
#pragma unroll
    for (int i = 0; i < 4; i++)
#pragma unroll
        for (int j = 0; j < 4; j++)
#pragma unroll
            for (int e = 0; e < 4; e++) acc[i][j][e] = 0.0f;

    const int S = g.K / BKH;
    g2_load(g, 0, m0, n0, z, smb, tid); CP_COMMIT();
    g2_load(g, 1, m0, n0, z, smb, tid); CP_COMMIT();

    for (int s = 0; s < S; s++) {
        CP_WAIT1();
        __syncthreads();
        if (s + 2 < S) g2_load(g, s + 2, m0, n0, z, smb, tid);
        CP_COMMIT();

        const uint32_t sb0 = smb + (uint32_t)((s % 3) * 3) * TILE_B;
        const uint32_t baseA  = sb0;
        const uint32_t baseBh = sb0 + 1 * TILE_B;
        const uint32_t baseBl = sb0 + 2 * TILE_B;
#pragma unroll
        for (int kk = 0; kk < 2; kk++) {
            uint32_t a[4][4];
#pragma unroll
            for (int i = 0; i < 4; i++) {
                uint32_t ao = (uint32_t)(
                    (wm * 64 + i * 16 + (lane & 15)) * LDS_ + kk * 16 + (lane >> 4) * 8) * 2;
                ldsm_x4(a[i][0], a[i][1], a[i][2], a[i][3], baseA + ao);
            }
#pragma unroll
            for (int j2 = 0; j2 < 2; j2++) {
                uint32_t bo = (uint32_t)(
                    (wn * 32 + j2 * 16 + (lane & 7) + ((lane >> 4) & 1) * 8) * LDS_
                    + kk * 16 + ((lane >> 3) & 1) * 8) * 2;
                uint32_t bh[2][2], bl[2][2];
                {
                    uint32_t t0, t1, t2, t3;
                    ldsm_x4(t0, t1, t2, t3, baseBh + bo);
                    bh[0][0] = t0; bh[0][1] = t1; bh[1][0] = t2; bh[1][1] = t3;
                    ldsm_x4(t0, t1, t2, t3, baseBl + bo);
                    bl[0][0] = t0; bl[0][1] = t1; bl[1][0] = t2; bl[1][1] = t3;
                }
#pragma unroll
                for (int jj = 0; jj < 2; jj++) {
                    const int j = 2 * j2 + jj;
#pragma unroll
                    for (int i = 0; i < 4; i++) mma16816(acc[i][j], a[i], bh[jj]);
#pragma unroll
                    for (int i = 0; i < 4; i++) mma16816(acc[i][j], a[i], bl[jj]);
                }
            }
        }
    }
    CP_WAIT0();
    epilogue<EPI>(acc, m0, n0, z, wm, wn, lane, outp, bias);
}

// ---------------- softmax (per row of logits), writes hi fp16 probs ----------------
__global__ __launch_bounds__(256) void softmax_kernel() {
    const long long row = blockIdx.x;
    const float* __restrict__ L = g_logits + row * (long long)NS;
    const int tid = threadIdx.x;

    float lv[8];
    float mx = -3.4e38f;
#pragma unroll
    for (int i = 0; i < 8; i++) {
        lv[i] = L[tid + i * 256];
        mx = fmaxf(mx, lv[i]);
    }
#pragma unroll
    for (int o = 16; o; o >>= 1) mx = fmaxf(mx, __shfl_xor_sync(0xffffffffu, mx, o));
    __shared__ float smax[8];
    __shared__ float ssum[8];
    if ((tid & 31) == 0) smax[tid >> 5] = mx;
    __syncthreads();
    float bmax = smax[0];
#pragma unroll
    for (int i = 1; i < 8; i++) bmax = fmaxf(bmax, smax[i]);

    float s = 0.0f;
#pragma unroll
    for (int i = 0; i < 8; i++) {
        lv[i] = __expf(lv[i] - bmax);
        s += lv[i];
    }
#pragma unroll
    for (int o = 16; o; o >>= 1) s += __shfl_xor_sync(0xffffffffu, s, o);
    if ((tid & 31) == 0) ssum[tid >> 5] = s;
    __syncthreads();
    float tot = 0.0f;
#pragma unroll
    for (int i = 0; i < 8; i++) tot += ssum[i];
    float inv = 1.0f / tot;

#pragma unroll
    for (int i = 0; i < 8; i++) {
        g_sh[row * NS + tid + i * 256] = __float2half_rn(lv[i] * inv);
    }
}

// ---------------- launch ----------------
extern "C" void kernel_launch(void* const* d_in, const int* in_sizes, int n_in,
                              void* d_out, int out_size) {
    const float *x = nullptr, *wq = nullptr, *ow = nullptr, *ob = nullptr;
    for (int i = 0; i < n_in; i++) {
        long long sz = in_sizes[i];
        if (sz == (long long)MTOT * DD)      x  = (const float*)d_in[i];
        else if (sz == (long long)DD * NQKV) wq = (const float*)d_in[i];
        else if (sz == (long long)DD * DD)   ow = (const float*)d_in[i];
        else if (sz == DD)                   ob = (const float*)d_in[i];
    }
    if (!x)  x  = (const float*)d_in[0];
    if (!wq) wq = (const float*)d_in[1];
    if (!ow) ow = (const float*)d_in[2];
    if (!ob) ob = (const float*)d_in[3];
    float* out = (float*)d_out;

    cudaFuncSetAttribute(mg_gemm1<EPI_QKV>,    cudaFuncAttributeMaxDynamicSharedMemorySize, SMEM_G1);
    cudaFuncSetAttribute(mg_gemm1<EPI_OUT>,    cudaFuncAttributeMaxDynamicSharedMemorySize, SMEM_G1);
    cudaFuncSetAttribute(mg_gemm2<EPI_LOGITS>, cudaFuncAttributeMaxDynamicSharedMemorySize, SMEM_G2);
    cudaFuncSetAttribute(mg_gemm2<EPI_YHI>,    cudaFuncAttributeMaxDynamicSharedMemorySize, SMEM_G2);

    prep_A<<<(int)(((long long)MTOT * KPQ + 255) / 256), 256>>>(x);
    prep_B<<<(int)(((long long)NQKV * KPQ + 255) / 256), 256>>>(wq);
    prep_OW<<<(DD * DD) / 256, 256>>>(ow);

    // 1) QKV: [16384 x 1536] * [3072 x 1536]^T -> hi/lo qkv (q pre-scaled)
    {
        G1 g{};
        g.aid = SEG_AP; g.aoff = 0; g.az = 0; g.lda = KPQ;
        g.bid = SEG_BP; g.boff = 0; g.bz = 0; g.ldb = KPQ;
        g.K = KPQ;
        mg_gemm1<EPI_QKV><<<dim3(NQKV / BN, MTOT / BM, 1), 256, SMEM_G1>>>(g, nullptr, nullptr);
    }
    // 1b) transpose V bands into [z][n][k]
    transpose_v<<<dim3(NS / 32, DD / 32, NB), dim3(32, 8)>>>();
    // 2) QK^T per batch: Qh*(Kh + Kl) -> fp32 logits
    {
        G2 g{};
        g.aid = SEG_QKVH; g.aoff = 0;
        g.bidh = SEG_QKVH; g.bidl = SEG_QKVL; g.boff = DD;
        g.lda = NQKV; g.ldb = NQKV;
        g.az = (long long)NS * NQKV; g.bz = (long long)NS * NQKV;
        g.K = DD;
        mg_gemm2<EPI_LOGITS><<<dim3(NS / BN, NS / BM, NB), 256, SMEM_G2>>>(g, nullptr, nullptr);
    }
    // 3) softmax rows -> hi probs
    softmax_kernel<<<MTOT, 256>>>();
    // 4) S*V per batch: Sh*(Vh + Vl) -> hi(y)
    {
        G2 g{};
        g.aid = SEG_SH; g.aoff = 0;
        g.bidh = SEG_VTH; g.bidl = SEG_VTL; g.boff = 0;
        g.lda = NS; g.ldb = NS;
        g.az = (long long)NS * NS; g.bz = (long long)DD * NS;
        g.K = NS;
        mg_gemm2<EPI_YHI><<<dim3(DD / BN, NS / BM, NB), 256, SMEM_G2>>>(g, nullptr, nullptr);
    }
    // 5) out = yh @ owh^T + b (single fp16 term)
    {
        G1 g{};
        g.aid = SEG_YH;  g.aoff = 0; g.az = 0; g.lda = DD;
        g.bid = SEG_OWH; g.boff = 0; g.bz = 0; g.ldb = DD;
        g.K = DD;
        mg_gemm1<EPI_OUT><<<dim3(DD / BN, MTOT / BM, 1), 256, SMEM_G1>>>(g, out, ob);
    }
}

// round 6
// speedup vs baseline: 3.3143x; 1.4798x over previous
#include <cuda_runtime.h>
#include <cuda_fp16.h>
#include <cstdint>

// Problem dims
#define DD    1024
#define NB    8
#define NS    2048
#define MTOT  (NB * NS)        // 16384
#define NQKV  (3 * DD)         // 3072

// GEMM tiling: block 128x128, 256 threads (8 warps, 2M x 4N), warp 64x32
#define BM 128
#define BN 128
#define BKH 32                 // K halves per stage
#define LDS_ 40                // padded smem stride (halves)
#define TILE_H (BM * LDS_)     // 5120 halves (10240 B) per tile
#define TILE_B (TILE_H * 2)
#define SMEM_G1 (8 * TILE_B)   // 4 stages x 2 tiles = 81920 B

// ---------------- scratch (device globals; no runtime allocation) ----------------
__device__ __align__(16) half  g_xh  [(size_t)MTOT * DD];      // fp16(x)           32 MB
__device__ __align__(16) half  g_wh  [(size_t)NQKV * DD];      // fp16(w^T) [n][k]   6 MB
__device__ __align__(16) half  g_qkvh[(size_t)MTOT * NQKV];    // fp16(qkv), q pre-scaled
__device__ __align__(16) float g_logits[(size_t)NB * NS * NS]; // attention logits 134 MB
__device__ __align__(16) half  g_sh [(size_t)NB * NS * NS];    // fp16(softmax)     67 MB
__device__ __align__(16) half  g_yh [(size_t)MTOT * DD];       // fp16(y)           33 MB
__device__ __align__(16) half  g_owh[(size_t)DD * DD];         // fp16(out_w) [n][k]
__device__ __align__(16) half  g_vth[(size_t)NB * DD * NS];    // fp16(V^T) [z][n][k] 33 MB

enum { SEG_XH = 0, SEG_WH, SEG_QKVH, SEG_SH, SEG_YH, SEG_OWH, SEG_VTH };

__device__ __forceinline__ const half* seg_ptr(int id) {
    switch (id) {
        case SEG_XH:   return g_xh;
        case SEG_WH:   return g_wh;
        case SEG_QKVH: return g_qkvh;
        case SEG_SH:   return g_sh;
        case SEG_YH:   return g_yh;
        case SEG_OWH:  return g_owh;
        case SEG_VTH:  return g_vth;
    }
    return nullptr;
}

// ---------------- PTX helpers ----------------
__device__ __forceinline__ uint32_t smem_u32(const void* p) {
    uint32_t a;
    asm("{ .reg .u64 t; cvta.to.shared.u64 t, %1; cvt.u32.u64 %0, t; }" : "=r"(a) : "l"(p));
    return a;
}

#define CP_ASYNC16(dst, src) \
    asm volatile("cp.async.cg.shared.global [%0], [%1], 16;\n" :: "r"(dst), "l"(src))
#define CP_COMMIT() asm volatile("cp.async.commit_group;\n" ::: "memory")
#define CP_WAIT2()  asm volatile("cp.async.wait_group 2;\n" ::: "memory")
#define CP_WAIT0()  asm volatile("cp.async.wait_group 0;\n" ::: "memory")

__device__ __forceinline__ void ldsm_x4(uint32_t& r0, uint32_t& r1, uint32_t& r2,
                                        uint32_t& r3, uint32_t addr) {
    asm volatile("ldmatrix.sync.aligned.m8n8.x4.shared.b16 {%0,%1,%2,%3}, [%4];"
                 : "=r"(r0), "=r"(r1), "=r"(r2), "=r"(r3) : "r"(addr));
}

__device__ __forceinline__ void mma16816(float* d, const uint32_t* a, const uint32_t* b) {
    asm volatile("mma.sync.aligned.m16n8k16.row.col.f32.f16.f16.f32 "
                 "{%0,%1,%2,%3}, {%4,%5,%6,%7}, {%8,%9}, {%0,%1,%2,%3};"
                 : "+f"(d[0]), "+f"(d[1]), "+f"(d[2]), "+f"(d[3])
                 : "r"(a[0]), "r"(a[1]), "r"(a[2]), "r"(a[3]), "r"(b[0]), "r"(b[1]));
}

// ---------------- prep kernels ----------------
__global__ void prep_X(const float* __restrict__ x) {
    long long idx = (long long)blockIdx.x * blockDim.x + threadIdx.x;
    if (idx >= (long long)MTOT * DD) return;
    g_xh[idx] = __float2half_rn(x[idx]);
}

// w is [DD][NQKV] row-major; we need B[n][k] = w[k][n] (k-contiguous)
__global__ void prep_W(const float* __restrict__ w) {
    long long idx = (long long)blockIdx.x * blockDim.x + threadIdx.x;
    if (idx >= (long long)NQKV * DD) return;
    int k = (int)(idx & (DD - 1));
    int n = (int)(idx >> 10);
    g_wh[idx] = __float2half_rn(w[(long long)k * NQKV + n]);
}

// out = y @ ow^T: B[n][k] = ow[n][k] -> straight cast
__global__ void prep_OW(const float* __restrict__ ow) {
    int idx = blockIdx.x * blockDim.x + threadIdx.x;
    if (idx >= DD * DD) return;
    g_owh[idx] = __float2half_rn(ow[idx]);
}

// V transpose: g_qkvh[z][k][2*DD + n] -> g_vth[z][n][k]
__global__ void transpose_v() {
    __shared__ half th[32][33];
    const int z  = blockIdx.z;
    const int k0 = blockIdx.x * 32;
    const int n0 = blockIdx.y * 32;
    const int tx = threadIdx.x;
    const int ty = threadIdx.y;
#pragma unroll
    for (int i = 0; i < 32; i += 8) {
        long long src = ((long long)(z * NS + k0 + ty + i)) * NQKV + 2 * DD + n0 + tx;
        th[ty + i][tx] = g_qkvh[src];
    }
    __syncthreads();
#pragma unroll
    for (int i = 0; i < 32; i += 8) {
        long long dst = ((long long)(z * DD + n0 + ty + i)) * NS + k0 + tx;
        g_vth[dst] = th[tx][ty + i];
    }
}

// ---------------- GEMM args ----------------
struct G1 { long long aoff, boff, az, bz; int aid, bid, lda, ldb, K; };

enum { EPI_QKV = 0, EPI_OUT = 1, EPI_LOGITS = 2, EPI_YHI = 3 };

// shared epilogue: acc[i][j] rows m0+wm*64+i*16+(lane>>2)+{0,8},
// cols n0+wn*32+j*8+(lane&3)*2+{0,1}
template <int EPI>
__device__ __forceinline__ void epilogue(float acc[4][4][4], int m0, int n0, int z,
                                         int wm, int wn, int lane,
                                         float* __restrict__ outp,
                                         const float* __restrict__ bias) {
    const int rbase = m0 + wm * 64 + (lane >> 2);
    const int cbase = n0 + wn * 32 + (lane & 3) * 2;
#pragma unroll
    for (int i = 0; i < 4; i++) {
#pragma unroll
        for (int j = 0; j < 4; j++) {
            const int c = cbase + j * 8;
#pragma unroll
            for (int h = 0; h < 2; h++) {
                const int rr = rbase + i * 16 + h * 8;
                float v0 = acc[i][j][2 * h + 0];
                float v1 = acc[i][j][2 * h + 1];
                if (EPI == EPI_QKV) {
                    const float sc = (c < DD) ? 0.03125f : 1.0f;
                    long long o = (long long)rr * NQKV + c;
                    *reinterpret_cast<half2*>(g_qkvh + o) =
                        __halves2half2(__float2half_rn(v0 * sc), __float2half_rn(v1 * sc));
                } else if (EPI == EPI_OUT) {
                    long long o = (long long)rr * DD + c;
                    *reinterpret_cast<float2*>(outp + o) =
                        make_float2(v0 + bias[c], v1 + bias[c + 1]);
                } else if (EPI == EPI_LOGITS) {
                    long long o = ((long long)(z * NS + rr)) * NS + c;
                    *reinterpret_cast<float2*>(g_logits + o) = make_float2(v0, v1);
                } else { // EPI_YHI
                    long long o = ((long long)(z * NS + rr)) * DD + c;
                    *reinterpret_cast<half2*>(g_yh + o) =
                        __halves2half2(__float2half_rn(v0), __float2half_rn(v1));
                }
            }
        }
    }
}

// ---------------- single-term GEMM: 4 stages x 2 tiles ----------------
__device__ __forceinline__ void g1_load(const G1& g, int s, int m0, int n0, int z,
                                        uint32_t smb, int tid) {
    const int k0 = s * BKH;
    const half* A = seg_ptr(g.aid) + (long long)z * g.az + g.aoff;
    const half* B = seg_ptr(g.bid) + (long long)z * g.bz + g.boff;
    const uint32_t sa = smb + (uint32_t)((s & 3) * 2 + 0) * TILE_B;
    const uint32_t sb = smb + (uint32_t)((s & 3) * 2 + 1) * TILE_B;
#pragma unroll
    for (int i = 0; i < 2; i++) {
        int c = tid + i * 256;
        int r = c >> 2;
        int kc = (c & 3) * 8;
        CP_ASYNC16(sa + (uint32_t)(r * LDS_ + kc) * 2, A + (long long)(m0 + r) * g.lda + k0 + kc);
        CP_ASYNC16(sb + (uint32_t)(r * LDS_ + kc) * 2, B + (long long)(n0 + r) * g.ldb + k0 + kc);
    }
}

template <int EPI>
__global__ __launch_bounds__(256, 2) void mg_gemm1(G1 g, float* __restrict__ outp,
                                                   const float* __restrict__ bias) {
    extern __shared__ half sm[];
    const uint32_t smb = smem_u32(sm);
    const int tid  = threadIdx.x;
    const int lane = tid & 31;
    const int wm = (tid >> 5) >> 2;    // 0..1
    const int wn = (tid >> 5) & 3;     // 0..3
    const int m0 = blockIdx.y * BM;
    const int n0 = blockIdx.x * BN;
    const int z  = blockIdx.z;

    float acc[4][4][4];
#pragma unroll
    for (int i = 0; i < 4; i++)
#pragma unroll
        for (int j = 0; j < 4; j++)
#pragma unroll
            for (int e = 0; e < 4; e++) acc[i][j][e] = 0.0f;

    const int S = g.K / BKH;
#pragma unroll
    for (int p = 0; p < 3; p++) { g1_load(g, p, m0, n0, z, smb, tid); CP_COMMIT(); }

    for (int s = 0; s < S; s++) {
        CP_WAIT2();
        __syncthreads();
        if (s + 3 < S) g1_load(g, s + 3, m0, n0, z, smb, tid);
        CP_COMMIT();

        const uint32_t baseA = smb + (uint32_t)((s & 3) * 2 + 0) * TILE_B;
        const uint32_t baseB = smb + (uint32_t)((s & 3) * 2 + 1) * TILE_B;
#pragma unroll
        for (int kk = 0; kk < 2; kk++) {
            uint32_t a[4][4];
#pragma unroll
            for (int i = 0; i < 4; i++) {
                uint32_t addr = baseA + (uint32_t)(
                    (wm * 64 + i * 16 + (lane & 15)) * LDS_ + kk * 16 + (lane >> 4) * 8) * 2;
                ldsm_x4(a[i][0], a[i][1], a[i][2], a[i][3], addr);
            }
#pragma unroll
            for (int j2 = 0; j2 < 2; j2++) {
                uint32_t b[2][2];
                uint32_t t0, t1, t2, t3;
                uint32_t addr = baseB + (uint32_t)(
                    (wn * 32 + j2 * 16 + (lane & 7) + ((lane >> 4) & 1) * 8) * LDS_
                    + kk * 16 + ((lane >> 3) & 1) * 8) * 2;
                ldsm_x4(t0, t1, t2, t3, addr);
                b[0][0] = t0; b[0][1] = t1; b[1][0] = t2; b[1][1] = t3;
#pragma unroll
                for (int jj = 0; jj < 2; jj++)
#pragma unroll
                    for (int i = 0; i < 4; i++) mma16816(acc[i][2 * j2 + jj], a[i], b[jj]);
            }
        }
    }
    CP_WAIT0();
    epilogue<EPI>(acc, m0, n0, z, wm, wn, lane, outp, bias);
}

// ---------------- softmax (per row of logits) -> fp16 probs ----------------
__global__ __launch_bounds__(256) void softmax_kernel() {
    const long long row = blockIdx.x;
    const float* __restrict__ L = g_logits + row * (long long)NS;
    const int tid = threadIdx.x;

    float lv[8];
    float mx = -3.4e38f;
#pragma unroll
    for (int i = 0; i < 8; i++) {
        lv[i] = L[tid + i * 256];
        mx = fmaxf(mx, lv[i]);
    }
#pragma unroll
    for (int o = 16; o; o >>= 1) mx = fmaxf(mx, __shfl_xor_sync(0xffffffffu, mx, o));
    __shared__ float smax[8];
    __shared__ float ssum[8];
    if ((tid & 31) == 0) smax[tid >> 5] = mx;
    __syncthreads();
    float bmax = smax[0];
#pragma unroll
    for (int i = 1; i < 8; i++) bmax = fmaxf(bmax, smax[i]);

    float s = 0.0f;
#pragma unroll
    for (int i = 0; i < 8; i++) {
        lv[i] = __expf(lv[i] - bmax);
        s += lv[i];
    }
#pragma unroll
    for (int o = 16; o; o >>= 1) s += __shfl_xor_sync(0xffffffffu, s, o);
    if ((tid & 31) == 0) ssum[tid >> 5] = s;
    __syncthreads();
    float tot = 0.0f;
#pragma unroll
    for (int i = 0; i < 8; i++) tot += ssum[i];
    float inv = 1.0f / tot;

#pragma unroll
    for (int i = 0; i < 8; i++) {
        g_sh[row * NS + tid + i * 256] = __float2half_rn(lv[i] * inv);
    }
}

// ---------------- launch ----------------
extern "C" void kernel_launch(void* const* d_in, const int* in_sizes, int n_in,
                              void* d_out, int out_size) {
    const float *x = nullptr, *wq = nullptr, *ow = nullptr, *ob = nullptr;
    for (int i = 0; i < n_in; i++) {
        long long sz = in_sizes[i];
        if (sz == (long long)MTOT * DD)      x  = (const float*)d_in[i];
        else if (sz == (long long)DD * NQKV) wq = (const float*)d_in[i];
        else if (sz == (long long)DD * DD)   ow = (const float*)d_in[i];
        else if (sz == DD)                   ob = (const float*)d_in[i];
    }
    if (!x)  x  = (const float*)d_in[0];
    if (!wq) wq = (const float*)d_in[1];
    if (!ow) ow = (const float*)d_in[2];
    if (!ob) ob = (const float*)d_in[3];
    float* out = (float*)d_out;

    cudaFuncSetAttribute(mg_gemm1<EPI_QKV>,    cudaFuncAttributeMaxDynamicSharedMemorySize, SMEM_G1);
    cudaFuncSetAttribute(mg_gemm1<EPI_OUT>,    cudaFuncAttributeMaxDynamicSharedMemorySize, SMEM_G1);
    cudaFuncSetAttribute(mg_gemm1<EPI_LOGITS>, cudaFuncAttributeMaxDynamicSharedMemorySize, SMEM_G1);
    cudaFuncSetAttribute(mg_gemm1<EPI_YHI>,    cudaFuncAttributeMaxDynamicSharedMemorySize, SMEM_G1);

    prep_X<<<(int)(((long long)MTOT * DD) / 256), 256>>>(x);
    prep_W<<<(int)(((long long)NQKV * DD) / 256), 256>>>(wq);
    prep_OW<<<(DD * DD) / 256, 256>>>(ow);

    // 1) QKV: [16384 x 1024] * [3072 x 1024]^T -> fp16 qkv (q pre-scaled)
    {
        G1 g{};
        g.aid = SEG_XH; g.aoff = 0; g.az = 0; g.lda = DD;
        g.bid = SEG_WH; g.boff = 0; g.bz = 0; g.ldb = DD;
        g.K = DD;
        mg_gemm1<EPI_QKV><<<dim3(NQKV / BN, MTOT / BM, 1), 256, SMEM_G1>>>(g, nullptr, nullptr);
    }
    // 1b) transpose V band into [z][n][k]
    transpose_v<<<dim3(NS / 32, DD / 32, NB), dim3(32, 8)>>>();
    // 2) QK^T per batch -> fp32 logits
    {
        G1 g{};
        g.aid = SEG_QKVH; g.aoff = 0;
        g.bid = SEG_QKVH; g.boff = DD;
        g.lda = NQKV; g.ldb = NQKV;
        g.az = (long long)NS * NQKV; g.bz = (long long)NS * NQKV;
        g.K = DD;
        mg_gemm1<EPI_LOGITS><<<dim3(NS / BN, NS / BM, NB), 256, SMEM_G1>>>(g, nullptr, nullptr);
    }
    // 3) softmax rows -> fp16 probs
    softmax_kernel<<<MTOT, 256>>>();
    // 4) S*V per batch -> fp16 y
    {
        G1 g{};
        g.aid = SEG_SH;  g.aoff = 0; g.lda = NS;
        g.bid = SEG_VTH; g.boff = 0; g.ldb = NS;
        g.az = (long long)NS * NS; g.bz = (long long)DD * NS;
        g.K = NS;
        mg_gemm1<EPI_YHI><<<dim3(DD / BN, NS / BM, NB), 256, SMEM_G1>>>(g, nullptr, nullptr);
    }
    // 5) out = yh @ owh^T + b
    {
        G1 g{};
        g.aid = SEG_YH;  g.aoff = 0; g.az = 0; g.lda = DD;
        g.bid = SEG_OWH; g.boff = 0; g.bz = 0; g.ldb = DD;
        g.K = DD;
        mg_gemm1<EPI_OUT><<<dim3(DD / BN, MTOT / BM, 1), 256, SMEM_G1>>>(g, out, ob);
    }
}